// round 4
// baseline (speedup 1.0000x reference)
#include <cuda_runtime.h>

// ---------------------------------------------------------------------------
// Problem constants (fixed shapes)
// ---------------------------------------------------------------------------
namespace {
constexpr int B_    = 2;
constexpr int T_    = 12;
constexpr int N_    = 512;     // nodes
constexpr int D_    = 512;     // model dim
constexpr int KH_   = 8;       // heads
constexpr int DH_   = 64;      // head dim
constexpr int DFF_  = 2048;    // ffn hidden
constexpr int BT_   = B_ * T_;         // 24
constexpr int ROWS_ = BT_ * N_;        // 12288 token rows

// attention smem: Qs 32x65, S 32x513, KV 64x65 (floats)
constexpr int ATT_SMEM_FLOATS = 32 * 65 + 32 * 513 + 64 * 65;  // 22656
constexpr int ATT_SMEM_BYTES  = ATT_SMEM_FLOATS * 4;           // 90624
}

// ---------------------------------------------------------------------------
// Scratch (static device globals: the sanctioned alloc-free scratch path)
// ---------------------------------------------------------------------------
__device__ __align__(16) float g_xn [ROWS_ * D_];
__device__ __align__(16) float g_q  [ROWS_ * D_];
__device__ __align__(16) float g_k  [ROWS_ * D_];
__device__ __align__(16) float g_v  [ROWS_ * D_];
__device__ __align__(16) float g_ao [ROWS_ * D_];
__device__ __align__(16) float g_x1 [ROWS_ * D_];
__device__ __align__(16) float g_h  [ROWS_ * D_];
__device__ __align__(16) float g_hid[ROWS_ * DFF_];
__device__ __align__(16) float g_bias[N_ * N_];

// ---------------------------------------------------------------------------
// Kernel 1: graph bias  bias[n][m] = a*softmax_row(relu(E En . Em)) + b*lap + mask
// one block per row n, 512 threads (one per m)
// ---------------------------------------------------------------------------
__global__ void bias_kernel(const float* __restrict__ E,
                            const float* __restrict__ lap,
                            const float* __restrict__ alphap,
                            const float* __restrict__ betap,
                            float* __restrict__ bias) {
    __shared__ float en[64];
    __shared__ float red[512];
    const int n = blockIdx.x;
    const int t = threadIdx.x;

    if (t < 64) en[t] = E[n * 64 + t];
    __syncthreads();

    const float* em = E + t * 64;
    float acc = 0.f;
#pragma unroll 16
    for (int j = 0; j < 64; j++) acc = fmaf(en[j], em[j], acc);
    float r = fmaxf(acc, 0.f);

    // row max
    red[t] = r;
    __syncthreads();
    for (int s = 256; s > 0; s >>= 1) {
        if (t < s) red[t] = fmaxf(red[t], red[t + s]);
        __syncthreads();
    }
    const float mx = red[0];
    __syncthreads();

    // row sum of exp
    const float e = __expf(r - mx);
    red[t] = e;
    __syncthreads();
    for (int s = 256; s > 0; s >>= 1) {
        if (t < s) red[t] += red[t + s];
        __syncthreads();
    }
    const float soft = e / red[0];

    const float lv   = lap[n * N_ + t];
    const float mask = (lv == 0.f) ? -1e9f : 0.f;
    bias[n * N_ + t] = (*alphap) * soft + (*betap) * lv + mask;
}

// ---------------------------------------------------------------------------
// Kernel 2: LayerNorm over last dim (512). one block (128 thr) per row.
// ---------------------------------------------------------------------------
__global__ void ln_kernel(const float* __restrict__ x,
                          const float* __restrict__ g,
                          const float* __restrict__ be,
                          float* __restrict__ y) {
    const int row = blockIdx.x;
    const int t   = threadIdx.x;  // 128
    const float4 v = ((const float4*)(x + (size_t)row * D_))[t];

    float s  = v.x + v.y + v.z + v.w;
    float ss = fmaf(v.x, v.x, fmaf(v.y, v.y, fmaf(v.z, v.z, v.w * v.w)));
#pragma unroll
    for (int o = 16; o; o >>= 1) {
        s  += __shfl_xor_sync(0xffffffffu, s,  o);
        ss += __shfl_xor_sync(0xffffffffu, ss, o);
    }
    __shared__ float sh_s[4], sh_ss[4];
    const int warp = t >> 5, lane = t & 31;
    if (lane == 0) { sh_s[warp] = s; sh_ss[warp] = ss; }
    __syncthreads();
    const float ts  = sh_s[0] + sh_s[1] + sh_s[2] + sh_s[3];
    const float tss = sh_ss[0] + sh_ss[1] + sh_ss[2] + sh_ss[3];

    const float mean = ts * (1.f / 512.f);
    const float var  = tss * (1.f / 512.f) - mean * mean;
    const float inv  = rsqrtf(var + 1e-5f);

    const float4 gv = ((const float4*)g)[t];
    const float4 bv = ((const float4*)be)[t];
    float4 o;
    o.x = (v.x - mean) * inv * gv.x + bv.x;
    o.y = (v.y - mean) * inv * gv.y + bv.y;
    o.z = (v.z - mean) * inv * gv.z + bv.z;
    o.w = (v.w - mean) * inv * gv.w + bv.w;
    ((float4*)(y + (size_t)row * D_))[t] = o;
}

// ---------------------------------------------------------------------------
// Kernel 3: SGEMM NT  C[M,Nc] = A[M,Kc] @ W[Nc,Kc]^T + bias (+res) (relu)
// 128x128 block tile, BK=8, 256 threads, 8x8 per-thread register tile.
// ---------------------------------------------------------------------------
template <bool RELU, bool HAS_RES>
__global__ __launch_bounds__(256, 2)
void gemm_nt(const float* __restrict__ A, const float* __restrict__ W,
             const float* __restrict__ bias, const float* __restrict__ res,
             float* __restrict__ C, int M, int Nc, int Kc) {
    __shared__ float As[8][128];
    __shared__ float Ws[8][128];

    const int bm  = blockIdx.y * 128;
    const int bn  = blockIdx.x * 128;
    const int tid = threadIdx.x;
    const int ty  = tid >> 4;        // 0..15
    const int tx  = tid & 15;        // 0..15
    const int lr  = tid >> 1;        // 0..127 load row
    const int lc  = (tid & 1) * 4;   // 0 or 4  load col (float4)

    const float* Ap = A + (size_t)(bm + lr) * Kc + lc;
    const float* Wp = W + (size_t)(bn + lr) * Kc + lc;

    float acc[8][8];
#pragma unroll
    for (int i = 0; i < 8; i++)
#pragma unroll
        for (int j = 0; j < 8; j++) acc[i][j] = 0.f;

    for (int k0 = 0; k0 < Kc; k0 += 8) {
        const float4 av = *(const float4*)(Ap + k0);
        const float4 wv = *(const float4*)(Wp + k0);
        __syncthreads();
        As[lc + 0][lr] = av.x; As[lc + 1][lr] = av.y;
        As[lc + 2][lr] = av.z; As[lc + 3][lr] = av.w;
        Ws[lc + 0][lr] = wv.x; Ws[lc + 1][lr] = wv.y;
        Ws[lc + 2][lr] = wv.z; Ws[lc + 3][lr] = wv.w;
        __syncthreads();
#pragma unroll
        for (int kk = 0; kk < 8; kk++) {
            float a[8], b[8];
            *(float4*)&a[0] = *(const float4*)&As[kk][ty * 8];
            *(float4*)&a[4] = *(const float4*)&As[kk][ty * 8 + 4];
            *(float4*)&b[0] = *(const float4*)&Ws[kk][tx * 8];
            *(float4*)&b[4] = *(const float4*)&Ws[kk][tx * 8 + 4];
#pragma unroll
            for (int i = 0; i < 8; i++)
#pragma unroll
                for (int j = 0; j < 8; j++)
                    acc[i][j] = fmaf(a[i], b[j], acc[i][j]);
        }
    }

    const float4 bi0 = *(const float4*)(bias + bn + tx * 8);
    const float4 bi1 = *(const float4*)(bias + bn + tx * 8 + 4);
    const float bb[8] = {bi0.x, bi0.y, bi0.z, bi0.w, bi1.x, bi1.y, bi1.z, bi1.w};

#pragma unroll
    for (int i = 0; i < 8; i++) {
        const size_t row = (size_t)(bm + ty * 8 + i);
        float* cp = C + row * Nc + bn + tx * 8;
        float o[8];
#pragma unroll
        for (int j = 0; j < 8; j++) o[j] = acc[i][j] + bb[j];
        if (HAS_RES) {
            const float* rp = res + row * Nc + bn + tx * 8;
            const float4 r0 = *(const float4*)rp;
            const float4 r1 = *(const float4*)(rp + 4);
            o[0] += r0.x; o[1] += r0.y; o[2] += r0.z; o[3] += r0.w;
            o[4] += r1.x; o[5] += r1.y; o[6] += r1.z; o[7] += r1.w;
        }
        if (RELU) {
#pragma unroll
            for (int j = 0; j < 8; j++) o[j] = fmaxf(o[j], 0.f);
        }
        *(float4*)cp       = make_float4(o[0], o[1], o[2], o[3]);
        *(float4*)(cp + 4) = make_float4(o[4], o[5], o[6], o[7]);
    }
}

// ---------------------------------------------------------------------------
// Kernel 4: attention. block = (head h, 32-query tile).
// S strip 32x512 lives in smem (rows padded to 513); bias fused; exact softmax.
// ---------------------------------------------------------------------------
__global__ __launch_bounds__(256)
void attn_kernel(const float* __restrict__ Q, const float* __restrict__ Kx,
                 const float* __restrict__ V, const float* __restrict__ bias,
                 float* __restrict__ O) {
    extern __shared__ float sm[];
    float* Qs = sm;                     // 32 x 65
    float* S  = sm + 32 * 65;           // 32 x 513
    float* KV = S + 32 * 513;           // 64 x 65

    const int tid  = threadIdx.x;
    const int hidx = blockIdx.y;        // 0..191
    const int bt   = hidx >> 3;
    const int kh   = hidx & 7;
    const int n0   = blockIdx.x * 32;
    const size_t rowbase = (size_t)bt * N_;
    const size_t headoff = (size_t)kh * DH_;

    // load Q tile, pre-scaled by 1/sqrt(64) = 0.125
    for (int i = tid; i < 32 * 16; i += 256) {
        const int r = i >> 4, c = (i & 15) << 2;
        const float4 vv = *(const float4*)(Q + (rowbase + n0 + r) * D_ + headoff + c);
        float* qd = Qs + r * 65 + c;
        qd[0] = vv.x * 0.125f; qd[1] = vv.y * 0.125f;
        qd[2] = vv.z * 0.125f; qd[3] = vv.w * 0.125f;
    }

    const int r2 = tid >> 4;            // 0..15
    const int i0 = r2 * 2, i1 = i0 + 1; // two query rows
    const int c4 = (tid & 15) << 2;     // 4 key cols

    // ---- phase 1: S = Q K^T * scale + bias -------------------------------
    for (int m0 = 0; m0 < N_; m0 += 64) {
        __syncthreads();
        for (int i = tid; i < 64 * 16; i += 256) {
            const int r = i >> 4, c = (i & 15) << 2;
            const float4 vv = *(const float4*)(Kx + (rowbase + m0 + r) * D_ + headoff + c);
            float* kd = KV + r * 65 + c;
            kd[0] = vv.x; kd[1] = vv.y; kd[2] = vv.z; kd[3] = vv.w;
        }
        __syncthreads();
        float a0[4] = {0.f, 0.f, 0.f, 0.f};
        float a1[4] = {0.f, 0.f, 0.f, 0.f};
#pragma unroll 16
        for (int dd = 0; dd < 64; dd++) {
            const float q0 = Qs[i0 * 65 + dd];
            const float q1 = Qs[i1 * 65 + dd];
#pragma unroll
            for (int j = 0; j < 4; j++) {
                const float kv = KV[(c4 + j) * 65 + dd];
                a0[j] = fmaf(q0, kv, a0[j]);
                a1[j] = fmaf(q1, kv, a1[j]);
            }
        }
        const float* b0 = bias + (size_t)(n0 + i0) * N_ + m0 + c4;
        const float* b1 = bias + (size_t)(n0 + i1) * N_ + m0 + c4;
        float* s0 = S + i0 * 513 + m0 + c4;
        float* s1 = S + i1 * 513 + m0 + c4;
#pragma unroll
        for (int j = 0; j < 4; j++) {
            s0[j] = a0[j] + b0[j];
            s1[j] = a1[j] + b1[j];
        }
    }
    __syncthreads();

    // ---- phase 2: exact row softmax (warp w owns rows 4w..4w+3) ----------
    {
        const int warp = tid >> 5, lane = tid & 31;
#pragma unroll
        for (int ii = 0; ii < 4; ii++) {
            float* row = S + (warp * 4 + ii) * 513;
            float mx = -3.4e38f;
            for (int m = lane; m < N_; m += 32) mx = fmaxf(mx, row[m]);
#pragma unroll
            for (int o = 16; o; o >>= 1) mx = fmaxf(mx, __shfl_xor_sync(0xffffffffu, mx, o));
            float sum = 0.f;
            for (int m = lane; m < N_; m += 32) {
                const float e = __expf(row[m] - mx);
                row[m] = e;
                sum += e;
            }
#pragma unroll
            for (int o = 16; o; o >>= 1) sum += __shfl_xor_sync(0xffffffffu, sum, o);
            const float inv = 1.f / sum;
            for (int m = lane; m < N_; m += 32) row[m] *= inv;
        }
    }

    // ---- phase 3: O = P V ------------------------------------------------
    float o0[4] = {0.f, 0.f, 0.f, 0.f};
    float o1[4] = {0.f, 0.f, 0.f, 0.f};
    for (int m0 = 0; m0 < N_; m0 += 64) {
        __syncthreads();
        for (int i = tid; i < 64 * 16; i += 256) {
            const int r = i >> 4, c = (i & 15) << 2;
            const float4 vv = *(const float4*)(V + (rowbase + m0 + r) * D_ + headoff + c);
            float* vd = KV + r * 65 + c;
            vd[0] = vv.x; vd[1] = vv.y; vd[2] = vv.z; vd[3] = vv.w;
        }
        __syncthreads();
        const float* s0 = S + i0 * 513 + m0;
        const float* s1 = S + i1 * 513 + m0;
#pragma unroll 16
        for (int mm = 0; mm < 64; mm++) {
            const float p0 = s0[mm];
            const float p1 = s1[mm];
#pragma unroll
            for (int j = 0; j < 4; j++) {
                const float vv = KV[mm * 65 + c4 + j];
                o0[j] = fmaf(p0, vv, o0[j]);
                o1[j] = fmaf(p1, vv, o1[j]);
            }
        }
    }
    float* op0 = O + (rowbase + n0 + i0) * D_ + headoff + c4;
    float* op1 = O + (rowbase + n0 + i1) * D_ + headoff + c4;
    *(float4*)op0 = make_float4(o0[0], o0[1], o0[2], o0[3]);
    *(float4*)op1 = make_float4(o1[0], o1[1], o1[2], o1[3]);
}

// ---------------------------------------------------------------------------
// Launch
// ---------------------------------------------------------------------------
extern "C" void kernel_launch(void* const* d_in, const int* in_sizes, int n_in,
                              void* d_out, int out_size) {
    (void)in_sizes; (void)n_in; (void)out_size;
    const float* x    = (const float*)d_in[0];
    const float* lap  = (const float*)d_in[1];
    const float* ne   = (const float*)d_in[2];
    const float* Wq   = (const float*)d_in[3];
    const float* bq   = (const float*)d_in[4];
    const float* Wk   = (const float*)d_in[5];
    const float* bk   = (const float*)d_in[6];
    const float* Wv   = (const float*)d_in[7];
    const float* bv   = (const float*)d_in[8];
    const float* Wo   = (const float*)d_in[9];
    const float* bo   = (const float*)d_in[10];
    const float* W1   = (const float*)d_in[11];
    const float* b1   = (const float*)d_in[12];
    const float* W2   = (const float*)d_in[13];
    const float* b2   = (const float*)d_in[14];
    const float* g1   = (const float*)d_in[15];
    const float* be1  = (const float*)d_in[16];
    const float* g2   = (const float*)d_in[17];
    const float* be2  = (const float*)d_in[18];
    const float* alp  = (const float*)d_in[19];
    const float* bet  = (const float*)d_in[20];
    // d_in[21] = k (unused by the reference)
    float* out = (float*)d_out;

    float *xn, *q, *k, *v, *ao, *x1, *h, *hid, *bias;
    cudaGetSymbolAddress((void**)&xn,   g_xn);
    cudaGetSymbolAddress((void**)&q,    g_q);
    cudaGetSymbolAddress((void**)&k,    g_k);
    cudaGetSymbolAddress((void**)&v,    g_v);
    cudaGetSymbolAddress((void**)&ao,   g_ao);
    cudaGetSymbolAddress((void**)&x1,   g_x1);
    cudaGetSymbolAddress((void**)&h,    g_h);
    cudaGetSymbolAddress((void**)&hid,  g_hid);
    cudaGetSymbolAddress((void**)&bias, g_bias);

    cudaFuncSetAttribute(attn_kernel,
                         cudaFuncAttributeMaxDynamicSharedMemorySize,
                         ATT_SMEM_BYTES);

    // 1) graph bias (b,t,k-invariant)
    bias_kernel<<<N_, N_>>>(ne, lap, alp, bet, bias);

    // 2) LN1
    ln_kernel<<<ROWS_, 128>>>(x, g1, be1, xn);

    // 3) Q/K/V projections
    const dim3 thr(256);
    gemm_nt<false, false><<<dim3(D_ / 128, ROWS_ / 128), thr>>>(xn, Wq, bq, nullptr, q, ROWS_, D_, D_);
    gemm_nt<false, false><<<dim3(D_ / 128, ROWS_ / 128), thr>>>(xn, Wk, bk, nullptr, k, ROWS_, D_, D_);
    gemm_nt<false, false><<<dim3(D_ / 128, ROWS_ / 128), thr>>>(xn, Wv, bv, nullptr, v, ROWS_, D_, D_);

    // 4) attention (192 heads x 16 query tiles)
    attn_kernel<<<dim3(N_ / 32, BT_ * KH_), thr, ATT_SMEM_BYTES>>>(q, k, v, bias, ao);

    // 5) output projection + residual (x)
    gemm_nt<false, true><<<dim3(D_ / 128, ROWS_ / 128), thr>>>(ao, Wo, bo, x, x1, ROWS_, D_, D_);

    // 6) LN2
    ln_kernel<<<ROWS_, 128>>>(x1, g2, be2, h);

    // 7) FFN1 with fused ReLU
    gemm_nt<true, false><<<dim3(DFF_ / 128, ROWS_ / 128), thr>>>(h, W1, b1, nullptr, hid, ROWS_, DFF_, D_);

    // 8) FFN2 + residual (x1) -> output
    gemm_nt<false, true><<<dim3(D_ / 128, ROWS_ / 128), thr>>>(hid, W2, b2, x1, out, ROWS_, D_, DFF_);
}

// round 7
// speedup vs baseline: 1.2083x; 1.2083x over previous
#include <cuda_runtime.h>

// ---------------------------------------------------------------------------
// Problem constants (fixed shapes)
// ---------------------------------------------------------------------------
namespace {
constexpr int B_    = 2;
constexpr int T_    = 12;
constexpr int N_    = 512;     // nodes
constexpr int D_    = 512;     // model dim
constexpr int KH_   = 8;       // heads
constexpr int DH_   = 64;      // head dim
constexpr int DFF_  = 2048;    // ffn hidden
constexpr int BT_   = B_ * T_;         // 24
constexpr int ROWS_ = BT_ * N_;        // 12288 token rows

// attention smem: Qs 32x65, S 32x513, KV 64x65 (floats)
constexpr int ATT_SMEM_FLOATS = 32 * 65 + 32 * 513 + 64 * 65;  // 22656
constexpr int ATT_SMEM_BYTES  = ATT_SMEM_FLOATS * 4;           // 90624

// tensor-core gemm smem: double-buffered A,B tiles [128][36] u32
constexpr int GEMM_TILE_U32  = 128 * 36;                        // 4608
constexpr int GEMM_SMEM_BYTES = 2 * 2 * GEMM_TILE_U32 * 4;      // 73728
}

// ---------------------------------------------------------------------------
// Scratch (static device globals: the sanctioned alloc-free scratch path)
// ---------------------------------------------------------------------------
__device__ __align__(16) float g_xn [ROWS_ * D_];
__device__ __align__(16) float g_q  [ROWS_ * D_];
__device__ __align__(16) float g_k  [ROWS_ * D_];
__device__ __align__(16) float g_v  [ROWS_ * D_];
__device__ __align__(16) float g_ao [ROWS_ * D_];
__device__ __align__(16) float g_x1 [ROWS_ * D_];
__device__ __align__(16) float g_h  [ROWS_ * D_];
__device__ __align__(16) float g_hid[ROWS_ * DFF_];
__device__ __align__(16) float g_bias[N_ * N_];

// ---------------------------------------------------------------------------
// fp32 -> tf32 (round to nearest)
// ---------------------------------------------------------------------------
__device__ __forceinline__ unsigned f2tf32(float x) {
    unsigned r;
    asm("cvt.rna.tf32.f32 %0, %1;" : "=r"(r) : "f"(x));
    return r;
}

// ---------------------------------------------------------------------------
// Kernel 1: graph bias  bias[n][m] = a*softmax_row(relu(En.Em)) + b*lap + mask
// ---------------------------------------------------------------------------
__global__ void bias_kernel(const float* __restrict__ E,
                            const float* __restrict__ lap,
                            const float* __restrict__ alphap,
                            const float* __restrict__ betap,
                            float* __restrict__ bias) {
    __shared__ float en[64];
    __shared__ float red[512];
    const int n = blockIdx.x;
    const int t = threadIdx.x;

    if (t < 64) en[t] = E[n * 64 + t];
    __syncthreads();

    const float* em = E + t * 64;
    float acc = 0.f;
#pragma unroll 16
    for (int j = 0; j < 64; j++) acc = fmaf(en[j], em[j], acc);
    float r = fmaxf(acc, 0.f);

    red[t] = r;
    __syncthreads();
    for (int s = 256; s > 0; s >>= 1) {
        if (t < s) red[t] = fmaxf(red[t], red[t + s]);
        __syncthreads();
    }
    const float mx = red[0];
    __syncthreads();

    const float e = __expf(r - mx);
    red[t] = e;
    __syncthreads();
    for (int s = 256; s > 0; s >>= 1) {
        if (t < s) red[t] += red[t + s];
        __syncthreads();
    }
    const float soft = e / red[0];

    const float lv   = lap[n * N_ + t];
    const float mask = (lv == 0.f) ? -1e9f : 0.f;
    bias[n * N_ + t] = (*alphap) * soft + (*betap) * lv + mask;
}

// ---------------------------------------------------------------------------
// Kernel 2: LayerNorm over last dim (512). one block (128 thr) per row.
// ---------------------------------------------------------------------------
__global__ void ln_kernel(const float* __restrict__ x,
                          const float* __restrict__ g,
                          const float* __restrict__ be,
                          float* __restrict__ y) {
    const int row = blockIdx.x;
    const int t   = threadIdx.x;  // 128
    const float4 v = ((const float4*)(x + (size_t)row * D_))[t];

    float s  = v.x + v.y + v.z + v.w;
    float ss = fmaf(v.x, v.x, fmaf(v.y, v.y, fmaf(v.z, v.z, v.w * v.w)));
#pragma unroll
    for (int o = 16; o; o >>= 1) {
        s  += __shfl_xor_sync(0xffffffffu, s,  o);
        ss += __shfl_xor_sync(0xffffffffu, ss, o);
    }
    __shared__ float sh_s[4], sh_ss[4];
    const int warp = t >> 5, lane = t & 31;
    if (lane == 0) { sh_s[warp] = s; sh_ss[warp] = ss; }
    __syncthreads();
    const float ts  = sh_s[0] + sh_s[1] + sh_s[2] + sh_s[3];
    const float tss = sh_ss[0] + sh_ss[1] + sh_ss[2] + sh_ss[3];

    const float mean = ts * (1.f / 512.f);
    const float var  = tss * (1.f / 512.f) - mean * mean;
    const float inv  = rsqrtf(var + 1e-5f);

    const float4 gv = ((const float4*)g)[t];
    const float4 bv = ((const float4*)be)[t];
    float4 o;
    o.x = (v.x - mean) * inv * gv.x + bv.x;
    o.y = (v.y - mean) * inv * gv.y + bv.y;
    o.z = (v.z - mean) * inv * gv.z + bv.z;
    o.w = (v.w - mean) * inv * gv.w + bv.w;
    ((float4*)(y + (size_t)row * D_))[t] = o;
}

// ---------------------------------------------------------------------------
// Kernel 3: TF32 tensor-core GEMM NT  C[M,Nc] = A[M,Kc] @ W[Nc,Kc]^T (+bias)(+res)(relu)
// 128x128 block tile, BK=32, 512 threads / 16 warps, warp tile 32x32.
// Smem stride 36 -> all fragment LDS conflict-free (bank = lane).
// ---------------------------------------------------------------------------
template <bool RELU, bool HAS_RES>
__global__ __launch_bounds__(512)
void gemm_tc(const float* __restrict__ A, const float* __restrict__ W,
             const float* __restrict__ bias, const float* __restrict__ res,
             float* __restrict__ C, int M, int Nc, int Kc) {
    extern __shared__ unsigned sm_u[];
    unsigned* As = sm_u;                          // [2][128*36]
    unsigned* Bs = sm_u + 2 * GEMM_TILE_U32;      // [2][128*36]

    const int tid  = threadIdx.x;
    const int bm   = blockIdx.y * 128;
    const int bn   = blockIdx.x * 128;
    const int warp = tid >> 5;
    const int lane = tid & 31;
    const int gid  = lane >> 2;     // 0..7
    const int t4   = lane & 3;      // 0..3
    const int wm   = (warp & 3) * 32;
    const int wn   = (warp >> 2) * 32;

    const int lr = tid >> 2;        // 0..127 (load row)
    const int lk = (tid & 3) * 8;   // 0,8,16,24 (k base)

    const float* Ap = A + (size_t)(bm + lr) * Kc + lk;
    const float* Wp = W + (size_t)(bn + lr) * Kc + lk;
    const int swoff = lr * 36 + lk;

    float acc[2][4][4];
#pragma unroll
    for (int i = 0; i < 2; i++)
#pragma unroll
        for (int j = 0; j < 4; j++)
#pragma unroll
            for (int c = 0; c < 4; c++) acc[i][j][c] = 0.f;

    const int stages = Kc >> 5;

    float4 ra0, ra1, rb0, rb1;
    // prologue: stage 0 -> buf 0
    ra0 = *(const float4*)(Ap);
    ra1 = *(const float4*)(Ap + 4);
    rb0 = *(const float4*)(Wp);
    rb1 = *(const float4*)(Wp + 4);
    {
        unsigned* aw = As + swoff;
        unsigned* bw = Bs + swoff;
        aw[0] = f2tf32(ra0.x); aw[1] = f2tf32(ra0.y); aw[2] = f2tf32(ra0.z); aw[3] = f2tf32(ra0.w);
        aw[4] = f2tf32(ra1.x); aw[5] = f2tf32(ra1.y); aw[6] = f2tf32(ra1.z); aw[7] = f2tf32(ra1.w);
        bw[0] = f2tf32(rb0.x); bw[1] = f2tf32(rb0.y); bw[2] = f2tf32(rb0.z); bw[3] = f2tf32(rb0.w);
        bw[4] = f2tf32(rb1.x); bw[5] = f2tf32(rb1.y); bw[6] = f2tf32(rb1.z); bw[7] = f2tf32(rb1.w);
    }
    __syncthreads();

    for (int s = 0; s < stages; s++) {
        const unsigned* Ab = As + (s & 1) * GEMM_TILE_U32;
        const unsigned* Bb = Bs + (s & 1) * GEMM_TILE_U32;

        if (s + 1 < stages) {
            const float* Ap2 = Ap + (s + 1) * 32;
            const float* Wp2 = Wp + (s + 1) * 32;
            ra0 = *(const float4*)(Ap2);
            ra1 = *(const float4*)(Ap2 + 4);
            rb0 = *(const float4*)(Wp2);
            rb1 = *(const float4*)(Wp2 + 4);
        }

#pragma unroll
        for (int ks = 0; ks < 4; ks++) {
            unsigned af[2][4], bf[4][2];
#pragma unroll
            for (int i = 0; i < 2; i++) {
                const unsigned* p = Ab + (wm + 16 * i + gid) * 36 + ks * 8 + t4;
                af[i][0] = p[0];
                af[i][1] = p[8 * 36];
                af[i][2] = p[4];
                af[i][3] = p[8 * 36 + 4];
            }
#pragma unroll
            for (int j = 0; j < 4; j++) {
                const unsigned* p = Bb + (wn + 8 * j + gid) * 36 + ks * 8 + t4;
                bf[j][0] = p[0];
                bf[j][1] = p[4];
            }
#pragma unroll
            for (int i = 0; i < 2; i++)
#pragma unroll
                for (int j = 0; j < 4; j++) {
                    asm volatile(
                        "mma.sync.aligned.m16n8k8.row.col.f32.tf32.tf32.f32 "
                        "{%0,%1,%2,%3}, {%4,%5,%6,%7}, {%8,%9}, {%0,%1,%2,%3};\n"
                        : "+f"(acc[i][j][0]), "+f"(acc[i][j][1]),
                          "+f"(acc[i][j][2]), "+f"(acc[i][j][3])
                        : "r"(af[i][0]), "r"(af[i][1]), "r"(af[i][2]), "r"(af[i][3]),
                          "r"(bf[j][0]), "r"(bf[j][1]));
                }
        }

        if (s + 1 < stages) {
            unsigned* aw = As + ((s + 1) & 1) * GEMM_TILE_U32 + swoff;
            unsigned* bw = Bs + ((s + 1) & 1) * GEMM_TILE_U32 + swoff;
            aw[0] = f2tf32(ra0.x); aw[1] = f2tf32(ra0.y); aw[2] = f2tf32(ra0.z); aw[3] = f2tf32(ra0.w);
            aw[4] = f2tf32(ra1.x); aw[5] = f2tf32(ra1.y); aw[6] = f2tf32(ra1.z); aw[7] = f2tf32(ra1.w);
            bw[0] = f2tf32(rb0.x); bw[1] = f2tf32(rb0.y); bw[2] = f2tf32(rb0.z); bw[3] = f2tf32(rb0.w);
            bw[4] = f2tf32(rb1.x); bw[5] = f2tf32(rb1.y); bw[6] = f2tf32(rb1.z); bw[7] = f2tf32(rb1.w);
            __syncthreads();
        }
    }

    // epilogue
#pragma unroll
    for (int i = 0; i < 2; i++) {
        const int r0 = bm + wm + 16 * i + gid;
#pragma unroll
        for (int j = 0; j < 4; j++) {
            const int col = bn + wn + 8 * j + 2 * t4;
            const float2 bv = *(const float2*)(bias + col);
            float o00 = acc[i][j][0] + bv.x;
            float o01 = acc[i][j][1] + bv.y;
            float o10 = acc[i][j][2] + bv.x;
            float o11 = acc[i][j][3] + bv.y;
            if (HAS_RES) {
                const float2 rv0 = *(const float2*)(res + (size_t)r0 * Nc + col);
                const float2 rv1 = *(const float2*)(res + (size_t)(r0 + 8) * Nc + col);
                o00 += rv0.x; o01 += rv0.y;
                o10 += rv1.x; o11 += rv1.y;
            }
            if (RELU) {
                o00 = fmaxf(o00, 0.f); o01 = fmaxf(o01, 0.f);
                o10 = fmaxf(o10, 0.f); o11 = fmaxf(o11, 0.f);
            }
            *(float2*)(C + (size_t)r0 * Nc + col)       = make_float2(o00, o01);
            *(float2*)(C + (size_t)(r0 + 8) * Nc + col) = make_float2(o10, o11);
        }
    }
}

// ---------------------------------------------------------------------------
// Kernel 4: attention. block = (head h, 32-query tile).
// S strip 32x512 lives in smem (rows padded to 513); bias fused; exact softmax.
// ---------------------------------------------------------------------------
__global__ __launch_bounds__(256)
void attn_kernel(const float* __restrict__ Q, const float* __restrict__ Kx,
                 const float* __restrict__ V, const float* __restrict__ bias,
                 float* __restrict__ O) {
    extern __shared__ float sm[];
    float* Qs = sm;                     // 32 x 65
    float* S  = sm + 32 * 65;           // 32 x 513
    float* KV = S + 32 * 513;           // 64 x 65

    const int tid  = threadIdx.x;
    const int hidx = blockIdx.y;        // 0..191
    const int bt   = hidx >> 3;
    const int kh   = hidx & 7;
    const int n0   = blockIdx.x * 32;
    const size_t rowbase = (size_t)bt * N_;
    const size_t headoff = (size_t)kh * DH_;

    for (int i = tid; i < 32 * 16; i += 256) {
        const int r = i >> 4, c = (i & 15) << 2;
        const float4 vv = *(const float4*)(Q + (rowbase + n0 + r) * D_ + headoff + c);
        float* qd = Qs + r * 65 + c;
        qd[0] = vv.x * 0.125f; qd[1] = vv.y * 0.125f;
        qd[2] = vv.z * 0.125f; qd[3] = vv.w * 0.125f;
    }

    const int r2 = tid >> 4;
    const int i0 = r2 * 2, i1 = i0 + 1;
    const int c4 = (tid & 15) << 2;

    // ---- phase 1: S = Q K^T * scale + bias -------------------------------
    for (int m0 = 0; m0 < N_; m0 += 64) {
        __syncthreads();
        for (int i = tid; i < 64 * 16; i += 256) {
            const int r = i >> 4, c = (i & 15) << 2;
            const float4 vv = *(const float4*)(Kx + (rowbase + m0 + r) * D_ + headoff + c);
            float* kd = KV + r * 65 + c;
            kd[0] = vv.x; kd[1] = vv.y; kd[2] = vv.z; kd[3] = vv.w;
        }
        __syncthreads();
        float a0[4] = {0.f, 0.f, 0.f, 0.f};
        float a1[4] = {0.f, 0.f, 0.f, 0.f};
#pragma unroll 16
        for (int dd = 0; dd < 64; dd++) {
            const float q0 = Qs[i0 * 65 + dd];
            const float q1 = Qs[i1 * 65 + dd];
#pragma unroll
            for (int j = 0; j < 4; j++) {
                const float kv = KV[(c4 + j) * 65 + dd];
                a0[j] = fmaf(q0, kv, a0[j]);
                a1[j] = fmaf(q1, kv, a1[j]);
            }
        }
        const float* b0 = bias + (size_t)(n0 + i0) * N_ + m0 + c4;
        const float* b1 = bias + (size_t)(n0 + i1) * N_ + m0 + c4;
        float* s0 = S + i0 * 513 + m0 + c4;
        float* s1 = S + i1 * 513 + m0 + c4;
#pragma unroll
        for (int j = 0; j < 4; j++) {
            s0[j] = a0[j] + b0[j];
            s1[j] = a1[j] + b1[j];
        }
    }
    __syncthreads();

    // ---- phase 2: exact row softmax --------------------------------------
    {
        const int warp = tid >> 5, lane = tid & 31;
#pragma unroll
        for (int ii = 0; ii < 4; ii++) {
            float* row = S + (warp * 4 + ii) * 513;
            float mx = -3.4e38f;
            for (int m = lane; m < N_; m += 32) mx = fmaxf(mx, row[m]);
#pragma unroll
            for (int o = 16; o; o >>= 1) mx = fmaxf(mx, __shfl_xor_sync(0xffffffffu, mx, o));
            float sum = 0.f;
            for (int m = lane; m < N_; m += 32) {
                const float e = __expf(row[m] - mx);
                row[m] = e;
                sum += e;
            }
#pragma unroll
            for (int o = 16; o; o >>= 1) sum += __shfl_xor_sync(0xffffffffu, sum, o);
            const float inv = 1.f / sum;
            for (int m = lane; m < N_; m += 32) row[m] *= inv;
        }
    }

    // ---- phase 3: O = P V ------------------------------------------------
    float o0[4] = {0.f, 0.f, 0.f, 0.f};
    float o1[4] = {0.f, 0.f, 0.f, 0.f};
    for (int m0 = 0; m0 < N_; m0 += 64) {
        __syncthreads();
        for (int i = tid; i < 64 * 16; i += 256) {
            const int r = i >> 4, c = (i & 15) << 2;
            const float4 vv = *(const float4*)(V + (rowbase + m0 + r) * D_ + headoff + c);
            float* vd = KV + r * 65 + c;
            vd[0] = vv.x; vd[1] = vv.y; vd[2] = vv.z; vd[3] = vv.w;
        }
        __syncthreads();
        const float* s0 = S + i0 * 513 + m0;
        const float* s1 = S + i1 * 513 + m0;
#pragma unroll 16
        for (int mm = 0; mm < 64; mm++) {
            const float p0 = s0[mm];
            const float p1 = s1[mm];
#pragma unroll
            for (int j = 0; j < 4; j++) {
                const float vv = KV[mm * 65 + c4 + j];
                o0[j] = fmaf(p0, vv, o0[j]);
                o1[j] = fmaf(p1, vv, o1[j]);
            }
        }
    }
    float* op0 = O + (rowbase + n0 + i0) * D_ + headoff + c4;
    float* op1 = O + (rowbase + n0 + i1) * D_ + headoff + c4;
    *(float4*)op0 = make_float4(o0[0], o0[1], o0[2], o0[3]);
    *(float4*)op1 = make_float4(o1[0], o1[1], o1[2], o1[3]);
}

// ---------------------------------------------------------------------------
// Launch
// ---------------------------------------------------------------------------
extern "C" void kernel_launch(void* const* d_in, const int* in_sizes, int n_in,
                              void* d_out, int out_size) {
    (void)in_sizes; (void)n_in; (void)out_size;
    const float* x    = (const float*)d_in[0];
    const float* lap  = (const float*)d_in[1];
    const float* ne   = (const float*)d_in[2];
    const float* Wq   = (const float*)d_in[3];
    const float* bq   = (const float*)d_in[4];
    const float* Wk   = (const float*)d_in[5];
    const float* bk   = (const float*)d_in[6];
    const float* Wv   = (const float*)d_in[7];
    const float* bv   = (const float*)d_in[8];
    const float* Wo   = (const float*)d_in[9];
    const float* bo   = (const float*)d_in[10];
    const float* W1   = (const float*)d_in[11];
    const float* b1   = (const float*)d_in[12];
    const float* W2   = (const float*)d_in[13];
    const float* b2   = (const float*)d_in[14];
    const float* g1   = (const float*)d_in[15];
    const float* be1  = (const float*)d_in[16];
    const float* g2   = (const float*)d_in[17];
    const float* be2  = (const float*)d_in[18];
    const float* alp  = (const float*)d_in[19];
    const float* bet  = (const float*)d_in[20];
    float* out = (float*)d_out;

    float *xn, *q, *k, *v, *ao, *x1, *h, *hid, *bias;
    cudaGetSymbolAddress((void**)&xn,   g_xn);
    cudaGetSymbolAddress((void**)&q,    g_q);
    cudaGetSymbolAddress((void**)&k,    g_k);
    cudaGetSymbolAddress((void**)&v,    g_v);
    cudaGetSymbolAddress((void**)&ao,   g_ao);
    cudaGetSymbolAddress((void**)&x1,   g_x1);
    cudaGetSymbolAddress((void**)&h,    g_h);
    cudaGetSymbolAddress((void**)&hid,  g_hid);
    cudaGetSymbolAddress((void**)&bias, g_bias);

    cudaFuncSetAttribute(attn_kernel,
                         cudaFuncAttributeMaxDynamicSharedMemorySize,
                         ATT_SMEM_BYTES);
    cudaFuncSetAttribute(gemm_tc<false, false>,
                         cudaFuncAttributeMaxDynamicSharedMemorySize,
                         GEMM_SMEM_BYTES);
    cudaFuncSetAttribute(gemm_tc<false, true>,
                         cudaFuncAttributeMaxDynamicSharedMemorySize,
                         GEMM_SMEM_BYTES);
    cudaFuncSetAttribute(gemm_tc<true, false>,
                         cudaFuncAttributeMaxDynamicSharedMemorySize,
                         GEMM_SMEM_BYTES);

    // 1) graph bias (b,t,k-invariant)
    bias_kernel<<<N_, N_>>>(ne, lap, alp, bet, bias);

    // 2) LN1
    ln_kernel<<<ROWS_, 128>>>(x, g1, be1, xn);

    // 3) Q/K/V projections (tf32 tensor cores)
    const dim3 thr(512);
    gemm_tc<false, false><<<dim3(D_ / 128, ROWS_ / 128), thr, GEMM_SMEM_BYTES>>>(xn, Wq, bq, nullptr, q, ROWS_, D_, D_);
    gemm_tc<false, false><<<dim3(D_ / 128, ROWS_ / 128), thr, GEMM_SMEM_BYTES>>>(xn, Wk, bk, nullptr, k, ROWS_, D_, D_);
    gemm_tc<false, false><<<dim3(D_ / 128, ROWS_ / 128), thr, GEMM_SMEM_BYTES>>>(xn, Wv, bv, nullptr, v, ROWS_, D_, D_);

    // 4) attention (192 heads x 16 query tiles)
    attn_kernel<<<dim3(N_ / 32, BT_ * KH_), dim3(256), ATT_SMEM_BYTES>>>(q, k, v, bias, ao);

    // 5) output projection + residual (x)
    gemm_tc<false, true><<<dim3(D_ / 128, ROWS_ / 128), thr, GEMM_SMEM_BYTES>>>(ao, Wo, bo, x, x1, ROWS_, D_, D_);

    // 6) LN2
    ln_kernel<<<ROWS_, 128>>>(x1, g2, be2, h);

    // 7) FFN1 with fused ReLU
    gemm_tc<true, false><<<dim3(DFF_ / 128, ROWS_ / 128), thr, GEMM_SMEM_BYTES>>>(h, W1, b1, nullptr, hid, ROWS_, DFF_, D_);

    // 8) FFN2 + residual (x1) -> output
    gemm_tc<false, true><<<dim3(D_ / 128, ROWS_ / 128), thr, GEMM_SMEM_BYTES>>>(hid, W2, b2, x1, out, ROWS_, D_, DFF_);
}

// round 10
// speedup vs baseline: 2.5120x; 2.0790x over previous
#include <cuda_runtime.h>

// ---------------------------------------------------------------------------
// Problem constants (fixed shapes)
// ---------------------------------------------------------------------------
namespace {
constexpr int B_    = 2;
constexpr int T_    = 12;
constexpr int N_    = 512;     // nodes
constexpr int D_    = 512;     // model dim
constexpr int KH_   = 8;       // heads
constexpr int DH_   = 64;      // head dim
constexpr int DFF_  = 2048;    // ffn hidden
constexpr int BT_   = B_ * T_;         // 24
constexpr int ROWS_ = BT_ * N_;        // 12288 token rows

// gemm: 3-stage cp.async pipeline, A/B tiles [128][36] fp32
constexpr int GEMM_TILE   = 128 * 36;                       // floats per tile
constexpr int GEMM_SMEM   = 3 * 2 * GEMM_TILE * 4;          // 110592 B

// attention smem (floats): Qs 32x68 (tf32), S 32x521 (fp32), stage 128x68
constexpr int ATT_Q_   = 32 * 68;       // 2176
constexpr int ATT_S_   = 32 * 521;      // 16672
constexpr int ATT_ST_  = 128 * 68;      // 8704 (also used as Vt[64][133]=8512)
constexpr int ATT_SMEM = (ATT_Q_ + ATT_S_ + ATT_ST_) * 4;   // 110208 B
}

// ---------------------------------------------------------------------------
// Scratch (static device globals: the sanctioned alloc-free scratch path)
// ---------------------------------------------------------------------------
__device__ __align__(16) float g_xn [ROWS_ * D_];
__device__ __align__(16) float g_q  [ROWS_ * D_];
__device__ __align__(16) float g_k  [ROWS_ * D_];
__device__ __align__(16) float g_v  [ROWS_ * D_];
__device__ __align__(16) float g_ao [ROWS_ * D_];
__device__ __align__(16) float g_x1 [ROWS_ * D_];
__device__ __align__(16) float g_h  [ROWS_ * D_];
__device__ __align__(16) float g_hid[ROWS_ * DFF_];
__device__ __align__(16) float g_bias[N_ * N_];

// ---------------------------------------------------------------------------
// helpers
// ---------------------------------------------------------------------------
__device__ __forceinline__ unsigned f2tf32(float x) {
    unsigned r;
    asm("cvt.rna.tf32.f32 %0, %1;" : "=r"(r) : "f"(x));
    return r;
}
__device__ __forceinline__ void cp16(unsigned dst, const void* src) {
    asm volatile("cp.async.cg.shared.global [%0], [%1], 16;\n" :: "r"(dst), "l"(src));
}
#define MMA_TF32(acc, af, bf)                                                  \
    asm volatile(                                                              \
        "mma.sync.aligned.m16n8k8.row.col.f32.tf32.tf32.f32 "                  \
        "{%0,%1,%2,%3}, {%4,%5,%6,%7}, {%8,%9}, {%0,%1,%2,%3};\n"              \
        : "+f"((acc)[0]), "+f"((acc)[1]), "+f"((acc)[2]), "+f"((acc)[3])       \
        : "r"((af)[0]), "r"((af)[1]), "r"((af)[2]), "r"((af)[3]),              \
          "r"((bf)[0]), "r"((bf)[1]))

// ---------------------------------------------------------------------------
// Kernel 1: graph bias  bias[n][m] = a*softmax_row(relu(En.Em)) + b*lap + mask
// ---------------------------------------------------------------------------
__global__ void bias_kernel(const float* __restrict__ E,
                            const float* __restrict__ lap,
                            const float* __restrict__ alphap,
                            const float* __restrict__ betap,
                            float* __restrict__ bias) {
    __shared__ float en[64];
    __shared__ float red[512];
    const int n = blockIdx.x;
    const int t = threadIdx.x;

    if (t < 64) en[t] = E[n * 64 + t];
    __syncthreads();

    const float* em = E + t * 64;
    float acc = 0.f;
#pragma unroll 16
    for (int j = 0; j < 64; j++) acc = fmaf(en[j], em[j], acc);
    float r = fmaxf(acc, 0.f);

    red[t] = r;
    __syncthreads();
    for (int s = 256; s > 0; s >>= 1) {
        if (t < s) red[t] = fmaxf(red[t], red[t + s]);
        __syncthreads();
    }
    const float mx = red[0];
    __syncthreads();

    const float e = __expf(r - mx);
    red[t] = e;
    __syncthreads();
    for (int s = 256; s > 0; s >>= 1) {
        if (t < s) red[t] += red[t + s];
        __syncthreads();
    }
    const float soft = e / red[0];

    const float lv   = lap[n * N_ + t];
    const float mask = (lv == 0.f) ? -1e9f : 0.f;
    bias[n * N_ + t] = (*alphap) * soft + (*betap) * lv + mask;
}

// ---------------------------------------------------------------------------
// Kernel 2: LayerNorm over last dim (512). one block (128 thr) per row.
// ---------------------------------------------------------------------------
__global__ void ln_kernel(const float* __restrict__ x,
                          const float* __restrict__ g,
                          const float* __restrict__ be,
                          float* __restrict__ y) {
    const int row = blockIdx.x;
    const int t   = threadIdx.x;  // 128
    const float4 v = ((const float4*)(x + (size_t)row * D_))[t];

    float s  = v.x + v.y + v.z + v.w;
    float ss = fmaf(v.x, v.x, fmaf(v.y, v.y, fmaf(v.z, v.z, v.w * v.w)));
#pragma unroll
    for (int o = 16; o; o >>= 1) {
        s  += __shfl_xor_sync(0xffffffffu, s,  o);
        ss += __shfl_xor_sync(0xffffffffu, ss, o);
    }
    __shared__ float sh_s[4], sh_ss[4];
    const int warp = t >> 5, lane = t & 31;
    if (lane == 0) { sh_s[warp] = s; sh_ss[warp] = ss; }
    __syncthreads();
    const float ts  = sh_s[0] + sh_s[1] + sh_s[2] + sh_s[3];
    const float tss = sh_ss[0] + sh_ss[1] + sh_ss[2] + sh_ss[3];

    const float mean = ts * (1.f / 512.f);
    const float var  = tss * (1.f / 512.f) - mean * mean;
    const float inv  = rsqrtf(var + 1e-5f);

    const float4 gv = ((const float4*)g)[t];
    const float4 bv = ((const float4*)be)[t];
    float4 o;
    o.x = (v.x - mean) * inv * gv.x + bv.x;
    o.y = (v.y - mean) * inv * gv.y + bv.y;
    o.z = (v.z - mean) * inv * gv.z + bv.z;
    o.w = (v.w - mean) * inv * gv.w + bv.w;
    ((float4*)(y + (size_t)row * D_))[t] = o;
}

// ---------------------------------------------------------------------------
// Kernel 3: TF32 tensor-core GEMM NT with cp.async 3-stage pipeline.
// C[M,Nc] = A[M,Kc] @ W[Nc,Kc]^T (+bias)(+res)(relu)
// 128x128 block tile, BK=32, 256 threads / 8 warps, warp tile 32x64.
// Raw fp32 staged in smem; tensor core truncates to tf32.
// ---------------------------------------------------------------------------
template <bool RELU, bool HAS_RES>
__global__ __launch_bounds__(256)
void gemm_tc(const float* __restrict__ A, const float* __restrict__ W,
             const float* __restrict__ bias, const float* __restrict__ res,
             float* __restrict__ C, int M, int Nc, int Kc) {
    extern __shared__ float smf[];
    const int tid  = threadIdx.x;
    const int warp = tid >> 5, lane = tid & 31;
    const int gid  = lane >> 2, t4 = lane & 3;
    const int wm   = (warp & 3) * 32;
    const int wn   = (warp >> 2) * 64;
    const int bm   = blockIdx.y * 128;
    const int bn   = blockIdx.x * 128;
    const int lr   = tid >> 1;          // 0..127
    const int lc   = (tid & 1) * 16;    // 0 or 16 (float index)

    const float* Ap = A + (size_t)(bm + lr) * Kc + lc;
    const float* Wp = W + (size_t)(bn + lr) * Kc + lc;
    const unsigned sbase = (unsigned)__cvta_generic_to_shared(smf);
    const unsigned soff  = (unsigned)(lr * 36 + lc) * 4u;
    const int stages = Kc >> 5;

    float acc[2][8][4];
#pragma unroll
    for (int i = 0; i < 2; i++)
#pragma unroll
        for (int j = 0; j < 8; j++)
#pragma unroll
            for (int c = 0; c < 4; c++) acc[i][j][c] = 0.f;

    // prologue: stages 0,1
#pragma unroll
    for (int s = 0; s < 2; s++) {
        const unsigned da = sbase + (unsigned)(s * 2 * GEMM_TILE) * 4u + soff;
        const unsigned db = da + (unsigned)GEMM_TILE * 4u;
        const float* a = Ap + s * 32;
        const float* w = Wp + s * 32;
#pragma unroll
        for (int e = 0; e < 4; e++) { cp16(da + e * 16, a + e * 4); cp16(db + e * 16, w + e * 4); }
        asm volatile("cp.async.commit_group;\n");
    }

    for (int s = 0; s < stages; s++) {
        if (s + 1 < stages) asm volatile("cp.async.wait_group 1;\n");
        else                asm volatile("cp.async.wait_group 0;\n");
        __syncthreads();

        if (s + 2 < stages) {
            const int sn = s + 2;
            const unsigned da = sbase + (unsigned)((sn % 3) * 2 * GEMM_TILE) * 4u + soff;
            const unsigned db = da + (unsigned)GEMM_TILE * 4u;
            const float* a = Ap + sn * 32;
            const float* w = Wp + sn * 32;
#pragma unroll
            for (int e = 0; e < 4; e++) { cp16(da + e * 16, a + e * 4); cp16(db + e * 16, w + e * 4); }
            asm volatile("cp.async.commit_group;\n");
        }

        const unsigned* Ab = (const unsigned*)(smf + (s % 3) * 2 * GEMM_TILE);
        const unsigned* Bb = Ab + GEMM_TILE;
#pragma unroll
        for (int ks = 0; ks < 4; ks++) {
            unsigned af[2][4], bf[8][2];
#pragma unroll
            for (int i = 0; i < 2; i++) {
                const unsigned* p = Ab + (wm + 16 * i + gid) * 36 + ks * 8 + t4;
                af[i][0] = p[0]; af[i][1] = p[8 * 36]; af[i][2] = p[4]; af[i][3] = p[8 * 36 + 4];
            }
#pragma unroll
            for (int j = 0; j < 8; j++) {
                const unsigned* p = Bb + (wn + 8 * j + gid) * 36 + ks * 8 + t4;
                bf[j][0] = p[0]; bf[j][1] = p[4];
            }
#pragma unroll
            for (int i = 0; i < 2; i++)
#pragma unroll
                for (int j = 0; j < 8; j++) MMA_TF32(acc[i][j], af[i], bf[j]);
        }
    }

    // epilogue
#pragma unroll
    for (int i = 0; i < 2; i++) {
        const int r0 = bm + wm + 16 * i + gid;
#pragma unroll
        for (int j = 0; j < 8; j++) {
            const int col = bn + wn + 8 * j + 2 * t4;
            const float2 bv = *(const float2*)(bias + col);
            float o00 = acc[i][j][0] + bv.x;
            float o01 = acc[i][j][1] + bv.y;
            float o10 = acc[i][j][2] + bv.x;
            float o11 = acc[i][j][3] + bv.y;
            if (HAS_RES) {
                const float2 rv0 = *(const float2*)(res + (size_t)r0 * Nc + col);
                const float2 rv1 = *(const float2*)(res + (size_t)(r0 + 8) * Nc + col);
                o00 += rv0.x; o01 += rv0.y;
                o10 += rv1.x; o11 += rv1.y;
            }
            if (RELU) {
                o00 = fmaxf(o00, 0.f); o01 = fmaxf(o01, 0.f);
                o10 = fmaxf(o10, 0.f); o11 = fmaxf(o11, 0.f);
            }
            *(float2*)(C + (size_t)r0 * Nc + col)       = make_float2(o00, o01);
            *(float2*)(C + (size_t)(r0 + 8) * Nc + col) = make_float2(o10, o11);
        }
    }
}

// ---------------------------------------------------------------------------
// Kernel 4: tensor-core attention. block = (head, 32-query tile), 256 thr.
// Phase1: S = Q K^T * scale + bias via tf32 mma (K staged in 128-key chunks).
// Phase2: exact row softmax in smem; P rewritten RNA-rounded tf32.
// Phase3: O = P V via tf32 mma; V staged TRANSPOSED (Vt[d][m]).
// ---------------------------------------------------------------------------
__global__ __launch_bounds__(256)
void attn_tc(const float* __restrict__ Q, const float* __restrict__ Kx,
             const float* __restrict__ V, const float* __restrict__ bias,
             float* __restrict__ O) {
    extern __shared__ float sm[];
    float*    Qs  = sm;                 // 32 x 68 (tf32 bits)
    float*    S   = sm + ATT_Q_;        // 32 x 521 (fp32, then tf32 probs)
    float*    ST  = S + ATT_S_;         // K: 128x68 / Vt: 64x133
    unsigned* Qu  = (unsigned*)Qs;
    unsigned* Su  = (unsigned*)S;
    unsigned* STu = (unsigned*)ST;

    const int tid  = threadIdx.x;
    const int warp = tid >> 5, lane = tid & 31;
    const int gid  = lane >> 2, t4 = lane & 3;
    const int hidx = blockIdx.y;        // 0..191
    const int bt   = hidx >> 3;
    const int kh   = hidx & 7;
    const int n0   = blockIdx.x * 32;
    const size_t rowbase = (size_t)bt * N_;
    const size_t headoff = (size_t)kh * DH_;

    // load Q tile (32 x 64), scale by 0.125, RNA->tf32
    for (int i = tid; i < 32 * 16; i += 256) {
        const int r = i >> 4, c = (i & 15) << 2;
        const float4 vv = *(const float4*)(Q + (rowbase + n0 + r) * D_ + headoff + c);
        unsigned* qd = Qu + r * 68 + c;
        qd[0] = f2tf32(vv.x * 0.125f); qd[1] = f2tf32(vv.y * 0.125f);
        qd[2] = f2tf32(vv.z * 0.125f); qd[3] = f2tf32(vv.w * 0.125f);
    }

    // ---- phase 1: S = Q K^T + bias (4 chunks of 128 keys) ----------------
    const int wn1 = warp * 16;          // key base within chunk
    for (int ch = 0; ch < 4; ch++) {
        const int m0 = ch * 128;
        __syncthreads();
        for (int i = tid; i < 128 * 16; i += 256) {
            const int r = i >> 4, c = (i & 15) << 2;
            const float4 vv = *(const float4*)(Kx + (rowbase + m0 + r) * D_ + headoff + c);
            unsigned* kd = STu + r * 68 + c;
            kd[0] = f2tf32(vv.x); kd[1] = f2tf32(vv.y);
            kd[2] = f2tf32(vv.z); kd[3] = f2tf32(vv.w);
        }
        __syncthreads();

        float acc[2][2][4];
#pragma unroll
        for (int i = 0; i < 2; i++)
#pragma unroll
            for (int j = 0; j < 2; j++)
#pragma unroll
                for (int c = 0; c < 4; c++) acc[i][j][c] = 0.f;

#pragma unroll
        for (int ks = 0; ks < 8; ks++) {
            unsigned af[2][4], bf[2][2];
#pragma unroll
            for (int i = 0; i < 2; i++) {
                const unsigned* p = Qu + (16 * i + gid) * 68 + ks * 8 + t4;
                af[i][0] = p[0]; af[i][1] = p[8 * 68]; af[i][2] = p[4]; af[i][3] = p[8 * 68 + 4];
            }
#pragma unroll
            for (int j = 0; j < 2; j++) {
                const unsigned* p = STu + (wn1 + 8 * j + gid) * 68 + ks * 8 + t4;
                bf[j][0] = p[0]; bf[j][1] = p[4];
            }
#pragma unroll
            for (int i = 0; i < 2; i++)
#pragma unroll
                for (int j = 0; j < 2; j++) MMA_TF32(acc[i][j], af[i], bf[j]);
        }

        // store S (+bias)
#pragma unroll
        for (int i = 0; i < 2; i++) {
            const int r0 = 16 * i + gid;
#pragma unroll
            for (int j = 0; j < 2; j++) {
                const int col = wn1 + 8 * j + 2 * t4;     // within chunk
                const float2 b0 = *(const float2*)(bias + (size_t)(n0 + r0) * N_ + m0 + col);
                const float2 b1 = *(const float2*)(bias + (size_t)(n0 + r0 + 8) * N_ + m0 + col);
                S[r0 * 521 + m0 + col]           = acc[i][j][0] + b0.x;
                S[r0 * 521 + m0 + col + 1]       = acc[i][j][1] + b0.y;
                S[(r0 + 8) * 521 + m0 + col]     = acc[i][j][2] + b1.x;
                S[(r0 + 8) * 521 + m0 + col + 1] = acc[i][j][3] + b1.y;
            }
        }
    }
    __syncthreads();

    // ---- phase 2: exact row softmax; rewrite P as RNA tf32 ---------------
    {
#pragma unroll
        for (int ii = 0; ii < 4; ii++) {
            float*    row  = S  + (warp * 4 + ii) * 521;
            unsigned* rowu = Su + (warp * 4 + ii) * 521;
            float mx = -3.4e38f;
            for (int m = lane; m < N_; m += 32) mx = fmaxf(mx, row[m]);
#pragma unroll
            for (int o = 16; o; o >>= 1) mx = fmaxf(mx, __shfl_xor_sync(0xffffffffu, mx, o));
            float sum = 0.f;
            for (int m = lane; m < N_; m += 32) {
                const float e = __expf(row[m] - mx);
                row[m] = e;
                sum += e;
            }
#pragma unroll
            for (int o = 16; o; o >>= 1) sum += __shfl_xor_sync(0xffffffffu, sum, o);
            const float inv = 1.f / sum;
            for (int m = lane; m < N_; m += 32) rowu[m] = f2tf32(row[m] * inv);
        }
    }

    // ---- phase 3: O = P V (V staged transposed, stride 133) --------------
    const int wd = warp * 8;            // d columns for this warp
    float acc3[2][4];
#pragma unroll
    for (int i = 0; i < 2; i++)
#pragma unroll
        for (int c = 0; c < 4; c++) acc3[i][c] = 0.f;

    for (int ch = 0; ch < 4; ch++) {
        const int m0 = ch * 128;
        __syncthreads();
        for (int i = tid; i < 128 * 16; i += 256) {
            const int r = i >> 4, c = (i & 15) << 2;
            const float4 vv = *(const float4*)(V + (rowbase + m0 + r) * D_ + headoff + c);
            STu[(c + 0) * 133 + r] = f2tf32(vv.x);
            STu[(c + 1) * 133 + r] = f2tf32(vv.y);
            STu[(c + 2) * 133 + r] = f2tf32(vv.z);
            STu[(c + 3) * 133 + r] = f2tf32(vv.w);
        }
        __syncthreads();

#pragma unroll
        for (int ks = 0; ks < 16; ks++) {
            unsigned af[2][4], bf[2];
#pragma unroll
            for (int i = 0; i < 2; i++) {
                const unsigned* p = Su + (16 * i + gid) * 521 + m0 + ks * 8 + t4;
                af[i][0] = p[0]; af[i][1] = p[8 * 521]; af[i][2] = p[4]; af[i][3] = p[8 * 521 + 4];
            }
            {
                const unsigned* p = STu + (wd + gid) * 133 + ks * 8 + t4;
                bf[0] = p[0]; bf[1] = p[4];
            }
#pragma unroll
            for (int i = 0; i < 2; i++) MMA_TF32(acc3[i], af[i], bf);
        }
    }

    // write O
#pragma unroll
    for (int i = 0; i < 2; i++) {
        const size_t r0 = rowbase + n0 + 16 * i + gid;
        const size_t col = headoff + wd + 2 * t4;
        *(float2*)(O + r0 * D_ + col)       = make_float2(acc3[i][0], acc3[i][1]);
        *(float2*)(O + (r0 + 8) * D_ + col) = make_float2(acc3[i][2], acc3[i][3]);
    }
}

// ---------------------------------------------------------------------------
// Launch
// ---------------------------------------------------------------------------
extern "C" void kernel_launch(void* const* d_in, const int* in_sizes, int n_in,
                              void* d_out, int out_size) {
    (void)in_sizes; (void)n_in; (void)out_size;
    const float* x    = (const float*)d_in[0];
    const float* lap  = (const float*)d_in[1];
    const float* ne   = (const float*)d_in[2];
    const float* Wq   = (const float*)d_in[3];
    const float* bq   = (const float*)d_in[4];
    const float* Wk   = (const float*)d_in[5];
    const float* bk   = (const float*)d_in[6];
    const float* Wv   = (const float*)d_in[7];
    const float* bv   = (const float*)d_in[8];
    const float* Wo   = (const float*)d_in[9];
    const float* bo   = (const float*)d_in[10];
    const float* W1   = (const float*)d_in[11];
    const float* b1   = (const float*)d_in[12];
    const float* W2   = (const float*)d_in[13];
    const float* b2   = (const float*)d_in[14];
    const float* g1   = (const float*)d_in[15];
    const float* be1  = (const float*)d_in[16];
    const float* g2   = (const float*)d_in[17];
    const float* be2  = (const float*)d_in[18];
    const float* alp  = (const float*)d_in[19];
    const float* bet  = (const float*)d_in[20];
    float* out = (float*)d_out;

    float *xn, *q, *k, *v, *ao, *x1, *h, *hid, *bias;
    cudaGetSymbolAddress((void**)&xn,   g_xn);
    cudaGetSymbolAddress((void**)&q,    g_q);
    cudaGetSymbolAddress((void**)&k,    g_k);
    cudaGetSymbolAddress((void**)&v,    g_v);
    cudaGetSymbolAddress((void**)&ao,   g_ao);
    cudaGetSymbolAddress((void**)&x1,   g_x1);
    cudaGetSymbolAddress((void**)&h,    g_h);
    cudaGetSymbolAddress((void**)&hid,  g_hid);
    cudaGetSymbolAddress((void**)&bias, g_bias);

    cudaFuncSetAttribute(attn_tc,
                         cudaFuncAttributeMaxDynamicSharedMemorySize, ATT_SMEM);
    cudaFuncSetAttribute(gemm_tc<false, false>,
                         cudaFuncAttributeMaxDynamicSharedMemorySize, GEMM_SMEM);
    cudaFuncSetAttribute(gemm_tc<false, true>,
                         cudaFuncAttributeMaxDynamicSharedMemorySize, GEMM_SMEM);
    cudaFuncSetAttribute(gemm_tc<true, false>,
                         cudaFuncAttributeMaxDynamicSharedMemorySize, GEMM_SMEM);

    // 1) graph bias (b,t,k-invariant)
    bias_kernel<<<N_, N_>>>(ne, lap, alp, bet, bias);

    // 2) LN1
    ln_kernel<<<ROWS_, 128>>>(x, g1, be1, xn);

    // 3) Q/K/V projections (tf32 tensor cores, cp.async pipeline)
    const dim3 thr(256);
    gemm_tc<false, false><<<dim3(D_ / 128, ROWS_ / 128), thr, GEMM_SMEM>>>(xn, Wq, bq, nullptr, q, ROWS_, D_, D_);
    gemm_tc<false, false><<<dim3(D_ / 128, ROWS_ / 128), thr, GEMM_SMEM>>>(xn, Wk, bk, nullptr, k, ROWS_, D_, D_);
    gemm_tc<false, false><<<dim3(D_ / 128, ROWS_ / 128), thr, GEMM_SMEM>>>(xn, Wv, bv, nullptr, v, ROWS_, D_, D_);

    // 4) attention (192 heads x 16 query tiles, tensor cores)
    attn_tc<<<dim3(N_ / 32, BT_ * KH_), thr, ATT_SMEM>>>(q, k, v, bias, ao);

    // 5) output projection + residual (x)
    gemm_tc<false, true><<<dim3(D_ / 128, ROWS_ / 128), thr, GEMM_SMEM>>>(ao, Wo, bo, x, x1, ROWS_, D_, D_);

    // 6) LN2
    ln_kernel<<<ROWS_, 128>>>(x1, g2, be2, h);

    // 7) FFN1 with fused ReLU
    gemm_tc<true, false><<<dim3(DFF_ / 128, ROWS_ / 128), thr, GEMM_SMEM>>>(h, W1, b1, nullptr, hid, ROWS_, DFF_, D_);

    // 8) FFN2 + residual (x1) -> output
    gemm_tc<false, true><<<dim3(D_ / 128, ROWS_ / 128), thr, GEMM_SMEM>>>(hid, W2, b2, x1, out, ROWS_, D_, DFF_);
}

// round 11
// speedup vs baseline: 2.5474x; 1.0141x over previous
#include <cuda_runtime.h>

// ---------------------------------------------------------------------------
// Problem constants (fixed shapes)
// ---------------------------------------------------------------------------
namespace {
constexpr int B_    = 2;
constexpr int T_    = 12;
constexpr int N_    = 512;     // nodes
constexpr int D_    = 512;     // model dim
constexpr int KH_   = 8;       // heads
constexpr int DH_   = 64;      // head dim
constexpr int DFF_  = 2048;    // ffn hidden
constexpr int BT_   = B_ * T_;         // 24
constexpr int ROWS_ = BT_ * N_;        // 12288 token rows

// gemm: 3-stage cp.async pipeline, A/B tiles [128][36] fp32
constexpr int GEMM_TILE   = 128 * 36;                       // floats per tile
constexpr int GEMM_SMEM   = 3 * 2 * GEMM_TILE * 4;          // 110592 B

// attention smem (floats): Qs 32x68 (tf32), S 32x521 (fp32), stage 128x68
constexpr int ATT_Q_   = 32 * 68;       // 2176
constexpr int ATT_S_   = 32 * 521;      // 16672
constexpr int ATT_ST_  = 128 * 68;      // 8704 (also used as Vt[64][133]=8512)
constexpr int ATT_SMEM = (ATT_Q_ + ATT_S_ + ATT_ST_) * 4;   // 110208 B
}

// ---------------------------------------------------------------------------
// Scratch (static device globals: the sanctioned alloc-free scratch path)
// ---------------------------------------------------------------------------
__device__ __align__(16) float g_xn [ROWS_ * D_];
__device__ __align__(16) float g_q  [ROWS_ * D_];
__device__ __align__(16) float g_k  [ROWS_ * D_];
__device__ __align__(16) float g_v  [ROWS_ * D_];
__device__ __align__(16) float g_ao [ROWS_ * D_];
__device__ __align__(16) float g_x1 [ROWS_ * D_];
__device__ __align__(16) float g_h  [ROWS_ * D_];
__device__ __align__(16) float g_hid[ROWS_ * DFF_];
__device__ __align__(16) float g_bias[N_ * N_];

// ---------------------------------------------------------------------------
// helpers
// ---------------------------------------------------------------------------
__device__ __forceinline__ unsigned f2tf32(float x) {
    unsigned r;
    asm("cvt.rna.tf32.f32 %0, %1;" : "=r"(r) : "f"(x));
    return r;
}
__device__ __forceinline__ void cp16(unsigned dst, const void* src) {
    asm volatile("cp.async.cg.shared.global [%0], [%1], 16;\n" :: "r"(dst), "l"(src));
}
#define MMA_TF32(acc, af, bf)                                                  \
    asm volatile(                                                              \
        "mma.sync.aligned.m16n8k8.row.col.f32.tf32.tf32.f32 "                  \
        "{%0,%1,%2,%3}, {%4,%5,%6,%7}, {%8,%9}, {%0,%1,%2,%3};\n"              \
        : "+f"((acc)[0]), "+f"((acc)[1]), "+f"((acc)[2]), "+f"((acc)[3])       \
        : "r"((af)[0]), "r"((af)[1]), "r"((af)[2]), "r"((af)[3]),              \
          "r"((bf)[0]), "r"((bf)[1]))

// ---------------------------------------------------------------------------
// Kernel 1: graph bias  bias[n][m] = a*softmax_row(relu(En.Em)) + b*lap + mask
// ---------------------------------------------------------------------------
__global__ void bias_kernel(const float* __restrict__ E,
                            const float* __restrict__ lap,
                            const float* __restrict__ alphap,
                            const float* __restrict__ betap,
                            float* __restrict__ bias) {
    __shared__ float en[64];
    __shared__ float red[512];
    const int n = blockIdx.x;
    const int t = threadIdx.x;

    if (t < 64) en[t] = E[n * 64 + t];
    __syncthreads();

    const float* em = E + t * 64;
    float acc = 0.f;
#pragma unroll 16
    for (int j = 0; j < 64; j++) acc = fmaf(en[j], em[j], acc);
    float r = fmaxf(acc, 0.f);

    red[t] = r;
    __syncthreads();
    for (int s = 256; s > 0; s >>= 1) {
        if (t < s) red[t] = fmaxf(red[t], red[t + s]);
        __syncthreads();
    }
    const float mx = red[0];
    __syncthreads();

    const float e = __expf(r - mx);
    red[t] = e;
    __syncthreads();
    for (int s = 256; s > 0; s >>= 1) {
        if (t < s) red[t] += red[t + s];
        __syncthreads();
    }
    const float soft = e / red[0];

    const float lv   = lap[n * N_ + t];
    const float mask = (lv == 0.f) ? -1e9f : 0.f;
    bias[n * N_ + t] = (*alphap) * soft + (*betap) * lv + mask;
}

// ---------------------------------------------------------------------------
// Kernel 2: LayerNorm over last dim (512). one block (128 thr) per row.
// ---------------------------------------------------------------------------
__global__ void ln_kernel(const float* __restrict__ x,
                          const float* __restrict__ g,
                          const float* __restrict__ be,
                          float* __restrict__ y) {
    const int row = blockIdx.x;
    const int t   = threadIdx.x;  // 128
    const float4 v = ((const float4*)(x + (size_t)row * D_))[t];

    float s  = v.x + v.y + v.z + v.w;
    float ss = fmaf(v.x, v.x, fmaf(v.y, v.y, fmaf(v.z, v.z, v.w * v.w)));
#pragma unroll
    for (int o = 16; o; o >>= 1) {
        s  += __shfl_xor_sync(0xffffffffu, s,  o);
        ss += __shfl_xor_sync(0xffffffffu, ss, o);
    }
    __shared__ float sh_s[4], sh_ss[4];
    const int warp = t >> 5, lane = t & 31;
    if (lane == 0) { sh_s[warp] = s; sh_ss[warp] = ss; }
    __syncthreads();
    const float ts  = sh_s[0] + sh_s[1] + sh_s[2] + sh_s[3];
    const float tss = sh_ss[0] + sh_ss[1] + sh_ss[2] + sh_ss[3];

    const float mean = ts * (1.f / 512.f);
    const float var  = tss * (1.f / 512.f) - mean * mean;
    const float inv  = rsqrtf(var + 1e-5f);

    const float4 gv = ((const float4*)g)[t];
    const float4 bv = ((const float4*)be)[t];
    float4 o;
    o.x = (v.x - mean) * inv * gv.x + bv.x;
    o.y = (v.y - mean) * inv * gv.y + bv.y;
    o.z = (v.z - mean) * inv * gv.z + bv.z;
    o.w = (v.w - mean) * inv * gv.w + bv.w;
    ((float4*)(y + (size_t)row * D_))[t] = o;
}

// ---------------------------------------------------------------------------
// GEMM body: TF32 tensor-core GEMM NT, cp.async 3-stage pipeline,
// register-level fragment double buffering.
// C[M,Nc] = A[M,Kc] @ W[Nc,Kc]^T (+bias)(+res)(relu)
// 128x128 block tile, BK=32, 256 threads / 8 warps, warp tile 32x64.
// ---------------------------------------------------------------------------
__device__ __forceinline__ void load_frags(const unsigned* __restrict__ Ab,
                                           const unsigned* __restrict__ Bb,
                                           int wm, int wn, int gid, int t4, int ks,
                                           unsigned af[2][4], unsigned bf[8][2]) {
#pragma unroll
    for (int i = 0; i < 2; i++) {
        const unsigned* p = Ab + (wm + 16 * i + gid) * 36 + ks * 8 + t4;
        af[i][0] = p[0]; af[i][1] = p[8 * 36]; af[i][2] = p[4]; af[i][3] = p[8 * 36 + 4];
    }
#pragma unroll
    for (int j = 0; j < 8; j++) {
        const unsigned* p = Bb + (wn + 8 * j + gid) * 36 + ks * 8 + t4;
        bf[j][0] = p[0]; bf[j][1] = p[4];
    }
}

template <bool RELU, bool HAS_RES>
__device__ __forceinline__
void gemm_body(const float* __restrict__ A, const float* __restrict__ W,
               const float* __restrict__ bias, const float* __restrict__ res,
               float* __restrict__ C, int Nc, int Kc, float* smf) {
    const int tid  = threadIdx.x;
    const int warp = tid >> 5, lane = tid & 31;
    const int gid  = lane >> 2, t4 = lane & 3;
    const int wm   = (warp & 3) * 32;
    const int wn   = (warp >> 2) * 64;
    const int bm   = blockIdx.y * 128;
    const int bn   = blockIdx.x * 128;
    const int lr   = tid >> 1;          // 0..127
    const int lc   = (tid & 1) * 16;    // 0 or 16 (float index)

    const float* Ap = A + (size_t)(bm + lr) * Kc + lc;
    const float* Wp = W + (size_t)(bn + lr) * Kc + lc;
    const unsigned sbase = (unsigned)__cvta_generic_to_shared(smf);
    const unsigned soff  = (unsigned)(lr * 36 + lc) * 4u;
    const int stages = Kc >> 5;

    float acc[2][8][4];
#pragma unroll
    for (int i = 0; i < 2; i++)
#pragma unroll
        for (int j = 0; j < 8; j++)
#pragma unroll
            for (int c = 0; c < 4; c++) acc[i][j][c] = 0.f;

    // prologue: stages 0,1
#pragma unroll
    for (int s = 0; s < 2; s++) {
        const unsigned da = sbase + (unsigned)(s * 2 * GEMM_TILE) * 4u + soff;
        const unsigned db = da + (unsigned)GEMM_TILE * 4u;
        const float* a = Ap + s * 32;
        const float* w = Wp + s * 32;
#pragma unroll
        for (int e = 0; e < 4; e++) { cp16(da + e * 16, a + e * 4); cp16(db + e * 16, w + e * 4); }
        asm volatile("cp.async.commit_group;\n");
    }

    for (int s = 0; s < stages; s++) {
        if (s + 1 < stages) asm volatile("cp.async.wait_group 1;\n");
        else                asm volatile("cp.async.wait_group 0;\n");
        __syncthreads();

        if (s + 2 < stages) {
            const int sn = s + 2;
            const unsigned da = sbase + (unsigned)((sn % 3) * 2 * GEMM_TILE) * 4u + soff;
            const unsigned db = da + (unsigned)GEMM_TILE * 4u;
            const float* a = Ap + sn * 32;
            const float* w = Wp + sn * 32;
#pragma unroll
            for (int e = 0; e < 4; e++) { cp16(da + e * 16, a + e * 4); cp16(db + e * 16, w + e * 4); }
            asm volatile("cp.async.commit_group;\n");
        }

        const unsigned* Ab = (const unsigned*)(smf + (s % 3) * 2 * GEMM_TILE);
        const unsigned* Bb = Ab + GEMM_TILE;

        // fragment double buffering across the 4 k8 steps
        unsigned af[2][2][4], bf[2][8][2];
        load_frags(Ab, Bb, wm, wn, gid, t4, 0, af[0], bf[0]);
#pragma unroll
        for (int ks = 0; ks < 4; ks++) {
            if (ks < 3)
                load_frags(Ab, Bb, wm, wn, gid, t4, ks + 1, af[(ks + 1) & 1], bf[(ks + 1) & 1]);
            const int cur = ks & 1;
#pragma unroll
            for (int i = 0; i < 2; i++)
#pragma unroll
                for (int j = 0; j < 8; j++) MMA_TF32(acc[i][j], af[cur][i], bf[cur][j]);
        }
    }

    // epilogue
#pragma unroll
    for (int i = 0; i < 2; i++) {
        const int r0 = bm + wm + 16 * i + gid;
#pragma unroll
        for (int j = 0; j < 8; j++) {
            const int col = bn + wn + 8 * j + 2 * t4;
            const float2 bv = *(const float2*)(bias + col);
            float o00 = acc[i][j][0] + bv.x;
            float o01 = acc[i][j][1] + bv.y;
            float o10 = acc[i][j][2] + bv.x;
            float o11 = acc[i][j][3] + bv.y;
            if (HAS_RES) {
                const float2 rv0 = *(const float2*)(res + (size_t)r0 * Nc + col);
                const float2 rv1 = *(const float2*)(res + (size_t)(r0 + 8) * Nc + col);
                o00 += rv0.x; o01 += rv0.y;
                o10 += rv1.x; o11 += rv1.y;
            }
            if (RELU) {
                o00 = fmaxf(o00, 0.f); o01 = fmaxf(o01, 0.f);
                o10 = fmaxf(o10, 0.f); o11 = fmaxf(o11, 0.f);
            }
            *(float2*)(C + (size_t)r0 * Nc + col)       = make_float2(o00, o01);
            *(float2*)(C + (size_t)(r0 + 8) * Nc + col) = make_float2(o10, o11);
        }
    }
}

template <bool RELU, bool HAS_RES>
__global__ __launch_bounds__(256, 2)
void gemm_tc(const float* __restrict__ A, const float* __restrict__ W,
             const float* __restrict__ bias, const float* __restrict__ res,
             float* __restrict__ C, int Nc, int Kc) {
    extern __shared__ float smf[];
    gemm_body<RELU, HAS_RES>(A, W, bias, res, C, Nc, Kc, smf);
}

// fused QKV: blockIdx.z selects weight/bias/output (shared A, one launch)
struct QKVArgs {
    const float* W[3];
    const float* b[3];
    float*       o[3];
};
__global__ __launch_bounds__(256, 2)
void gemm_qkv(const float* __restrict__ A, QKVArgs args) {
    extern __shared__ float smf[];
    const int z = blockIdx.z;
    gemm_body<false, false>(A, args.W[z], args.b[z], nullptr, args.o[z], D_, D_, smf);
}

// ---------------------------------------------------------------------------
// Kernel 4: tensor-core attention. block = (head, 32-query tile), 256 thr.
// Phase1: S = Q K^T * scale + bias via tf32 mma (K cp.async-staged, truncated).
// Phase2: exact row softmax in smem; P rewritten RNA-rounded tf32.
// Phase3: O = P V via tf32 mma; V staged TRANSPOSED (Vt[d][m]).
// ---------------------------------------------------------------------------
__global__ __launch_bounds__(256)
void attn_tc(const float* __restrict__ Q, const float* __restrict__ Kx,
             const float* __restrict__ V, const float* __restrict__ bias,
             float* __restrict__ O) {
    extern __shared__ float sm[];
    float*    Qs  = sm;                 // 32 x 68 (tf32 bits)
    float*    S   = sm + ATT_Q_;        // 32 x 521 (fp32, then tf32 probs)
    float*    ST  = S + ATT_S_;         // K: 128x68 / Vt: 64x133
    unsigned* Qu  = (unsigned*)Qs;
    unsigned* Su  = (unsigned*)S;
    unsigned* STu = (unsigned*)ST;

    const int tid  = threadIdx.x;
    const int warp = tid >> 5, lane = tid & 31;
    const int gid  = lane >> 2, t4 = lane & 3;
    const int hidx = blockIdx.y;        // 0..191
    const int bt   = hidx >> 3;
    const int kh   = hidx & 7;
    const int n0   = blockIdx.x * 32;
    const size_t rowbase = (size_t)bt * N_;
    const size_t headoff = (size_t)kh * DH_;
    const unsigned stbase = (unsigned)__cvta_generic_to_shared(ST);

    // load Q tile (32 x 64), scale by 0.125, RNA->tf32
    for (int i = tid; i < 32 * 16; i += 256) {
        const int r = i >> 4, c = (i & 15) << 2;
        const float4 vv = *(const float4*)(Q + (rowbase + n0 + r) * D_ + headoff + c);
        unsigned* qd = Qu + r * 68 + c;
        qd[0] = f2tf32(vv.x * 0.125f); qd[1] = f2tf32(vv.y * 0.125f);
        qd[2] = f2tf32(vv.z * 0.125f); qd[3] = f2tf32(vv.w * 0.125f);
    }

    // ---- phase 1: S = Q K^T + bias (4 chunks of 128 keys) ----------------
    const int wn1 = warp * 16;          // key base within chunk
    for (int ch = 0; ch < 4; ch++) {
        const int m0 = ch * 128;
        __syncthreads();
        // cp.async K chunk (raw fp32; tensor core truncates to tf32)
        for (int i = tid; i < 128 * 4; i += 256) {
            const int r = i >> 2, c = (i & 3) << 4;   // 4 x 16-float segments? no: 4 x cp16 per row
            const unsigned dst = stbase + (unsigned)(r * 68 + c) * 4u;
            cp16(dst, Kx + (rowbase + m0 + r) * D_ + headoff + c);
            cp16(dst + 16, Kx + (rowbase + m0 + r) * D_ + headoff + c + 4);
            cp16(dst + 32, Kx + (rowbase + m0 + r) * D_ + headoff + c + 8);
            cp16(dst + 48, Kx + (rowbase + m0 + r) * D_ + headoff + c + 12);
        }
        asm volatile("cp.async.commit_group;\n");
        asm volatile("cp.async.wait_group 0;\n");
        __syncthreads();

        float acc[2][2][4];
#pragma unroll
        for (int i = 0; i < 2; i++)
#pragma unroll
            for (int j = 0; j < 2; j++)
#pragma unroll
                for (int c = 0; c < 4; c++) acc[i][j][c] = 0.f;

#pragma unroll
        for (int ks = 0; ks < 8; ks++) {
            unsigned af[2][4], bf[2][2];
#pragma unroll
            for (int i = 0; i < 2; i++) {
                const unsigned* p = Qu + (16 * i + gid) * 68 + ks * 8 + t4;
                af[i][0] = p[0]; af[i][1] = p[8 * 68]; af[i][2] = p[4]; af[i][3] = p[8 * 68 + 4];
            }
#pragma unroll
            for (int j = 0; j < 2; j++) {
                const unsigned* p = STu + (wn1 + 8 * j + gid) * 68 + ks * 8 + t4;
                bf[j][0] = p[0]; bf[j][1] = p[4];
            }
#pragma unroll
            for (int i = 0; i < 2; i++)
#pragma unroll
                for (int j = 0; j < 2; j++) MMA_TF32(acc[i][j], af[i], bf[j]);
        }

        // store S (+bias)
#pragma unroll
        for (int i = 0; i < 2; i++) {
            const int r0 = 16 * i + gid;
#pragma unroll
            for (int j = 0; j < 2; j++) {
                const int col = wn1 + 8 * j + 2 * t4;     // within chunk
                const float2 b0 = *(const float2*)(bias + (size_t)(n0 + r0) * N_ + m0 + col);
                const float2 b1 = *(const float2*)(bias + (size_t)(n0 + r0 + 8) * N_ + m0 + col);
                S[r0 * 521 + m0 + col]           = acc[i][j][0] + b0.x;
                S[r0 * 521 + m0 + col + 1]       = acc[i][j][1] + b0.y;
                S[(r0 + 8) * 521 + m0 + col]     = acc[i][j][2] + b1.x;
                S[(r0 + 8) * 521 + m0 + col + 1] = acc[i][j][3] + b1.y;
            }
        }
    }
    __syncthreads();

    // ---- phase 2: exact row softmax; rewrite P as RNA tf32 ---------------
    {
#pragma unroll
        for (int ii = 0; ii < 4; ii++) {
            float*    row  = S  + (warp * 4 + ii) * 521;
            unsigned* rowu = Su + (warp * 4 + ii) * 521;
            float mx = -3.4e38f;
            for (int m = lane; m < N_; m += 32) mx = fmaxf(mx, row[m]);
#pragma unroll
            for (int o = 16; o; o >>= 1) mx = fmaxf(mx, __shfl_xor_sync(0xffffffffu, mx, o));
            float sum = 0.f;
            for (int m = lane; m < N_; m += 32) {
                const float e = __expf(row[m] - mx);
                row[m] = e;
                sum += e;
            }
#pragma unroll
            for (int o = 16; o; o >>= 1) sum += __shfl_xor_sync(0xffffffffu, sum, o);
            const float inv = 1.f / sum;
            for (int m = lane; m < N_; m += 32) rowu[m] = f2tf32(row[m] * inv);
        }
    }

    // ---- phase 3: O = P V (V staged transposed, stride 133) --------------
    const int wd = warp * 8;            // d columns for this warp
    float acc3[2][4];
#pragma unroll
    for (int i = 0; i < 2; i++)
#pragma unroll
        for (int c = 0; c < 4; c++) acc3[i][c] = 0.f;

    for (int ch = 0; ch < 4; ch++) {
        const int m0 = ch * 128;
        __syncthreads();
        for (int i = tid; i < 128 * 16; i += 256) {
            const int r = i >> 4, c = (i & 15) << 2;
            const float4 vv = *(const float4*)(V + (rowbase + m0 + r) * D_ + headoff + c);
            STu[(c + 0) * 133 + r] = f2tf32(vv.x);
            STu[(c + 1) * 133 + r] = f2tf32(vv.y);
            STu[(c + 2) * 133 + r] = f2tf32(vv.z);
            STu[(c + 3) * 133 + r] = f2tf32(vv.w);
        }
        __syncthreads();

#pragma unroll
        for (int ks = 0; ks < 16; ks++) {
            unsigned af[2][4], bf[2];
#pragma unroll
            for (int i = 0; i < 2; i++) {
                const unsigned* p = Su + (16 * i + gid) * 521 + m0 + ks * 8 + t4;
                af[i][0] = p[0]; af[i][1] = p[8 * 521]; af[i][2] = p[4]; af[i][3] = p[8 * 521 + 4];
            }
            {
                const unsigned* p = STu + (wd + gid) * 133 + ks * 8 + t4;
                bf[0] = p[0]; bf[1] = p[4];
            }
#pragma unroll
            for (int i = 0; i < 2; i++) MMA_TF32(acc3[i], af[i], bf);
        }
    }

    // write O
#pragma unroll
    for (int i = 0; i < 2; i++) {
        const size_t r0 = rowbase + n0 + 16 * i + gid;
        const size_t col = headoff + wd + 2 * t4;
        *(float2*)(O + r0 * D_ + col)       = make_float2(acc3[i][0], acc3[i][1]);
        *(float2*)(O + (r0 + 8) * D_ + col) = make_float2(acc3[i][2], acc3[i][3]);
    }
}

// ---------------------------------------------------------------------------
// Launch
// ---------------------------------------------------------------------------
extern "C" void kernel_launch(void* const* d_in, const int* in_sizes, int n_in,
                              void* d_out, int out_size) {
    (void)in_sizes; (void)n_in; (void)out_size;
    const float* x    = (const float*)d_in[0];
    const float* lap  = (const float*)d_in[1];
    const float* ne   = (const float*)d_in[2];
    const float* Wq   = (const float*)d_in[3];
    const float* bq   = (const float*)d_in[4];
    const float* Wk   = (const float*)d_in[5];
    const float* bk   = (const float*)d_in[6];
    const float* Wv   = (const float*)d_in[7];
    const float* bv   = (const float*)d_in[8];
    const float* Wo   = (const float*)d_in[9];
    const float* bo   = (const float*)d_in[10];
    const float* W1   = (const float*)d_in[11];
    const float* b1   = (const float*)d_in[12];
    const float* W2   = (const float*)d_in[13];
    const float* b2   = (const float*)d_in[14];
    const float* g1   = (const float*)d_in[15];
    const float* be1  = (const float*)d_in[16];
    const float* g2   = (const float*)d_in[17];
    const float* be2  = (const float*)d_in[18];
    const float* alp  = (const float*)d_in[19];
    const float* bet  = (const float*)d_in[20];
    float* out = (float*)d_out;

    float *xn, *q, *k, *v, *ao, *x1, *h, *hid, *bias;
    cudaGetSymbolAddress((void**)&xn,   g_xn);
    cudaGetSymbolAddress((void**)&q,    g_q);
    cudaGetSymbolAddress((void**)&k,    g_k);
    cudaGetSymbolAddress((void**)&v,    g_v);
    cudaGetSymbolAddress((void**)&ao,   g_ao);
    cudaGetSymbolAddress((void**)&x1,   g_x1);
    cudaGetSymbolAddress((void**)&h,    g_h);
    cudaGetSymbolAddress((void**)&hid,  g_hid);
    cudaGetSymbolAddress((void**)&bias, g_bias);

    cudaFuncSetAttribute(attn_tc,
                         cudaFuncAttributeMaxDynamicSharedMemorySize, ATT_SMEM);
    cudaFuncSetAttribute(gemm_qkv,
                         cudaFuncAttributeMaxDynamicSharedMemorySize, GEMM_SMEM);
    cudaFuncSetAttribute(gemm_tc<false, false>,
                         cudaFuncAttributeMaxDynamicSharedMemorySize, GEMM_SMEM);
    cudaFuncSetAttribute(gemm_tc<false, true>,
                         cudaFuncAttributeMaxDynamicSharedMemorySize, GEMM_SMEM);
    cudaFuncSetAttribute(gemm_tc<true, false>,
                         cudaFuncAttributeMaxDynamicSharedMemorySize, GEMM_SMEM);

    // 1) graph bias (b,t,k-invariant)
    bias_kernel<<<N_, N_>>>(ne, lap, alp, bet, bias);

    // 2) LN1
    ln_kernel<<<ROWS_, 128>>>(x, g1, be1, xn);

    // 3) Q/K/V projections — fused single launch (shared A, 3x L2 reuse)
    const dim3 thr(256);
    QKVArgs qa;
    qa.W[0] = Wq; qa.W[1] = Wk; qa.W[2] = Wv;
    qa.b[0] = bq; qa.b[1] = bk; qa.b[2] = bv;
    qa.o[0] = q;  qa.o[1] = k;  qa.o[2] = v;
    gemm_qkv<<<dim3(D_ / 128, ROWS_ / 128, 3), thr, GEMM_SMEM>>>(xn, qa);

    // 4) attention (192 heads x 16 query tiles, tensor cores)
    attn_tc<<<dim3(N_ / 32, BT_ * KH_), thr, ATT_SMEM>>>(q, k, v, bias, ao);

    // 5) output projection + residual (x)
    gemm_tc<false, true><<<dim3(D_ / 128, ROWS_ / 128), thr, GEMM_SMEM>>>(ao, Wo, bo, x, x1, D_, D_);

    // 6) LN2
    ln_kernel<<<ROWS_, 128>>>(x1, g2, be2, h);

    // 7) FFN1 with fused ReLU
    gemm_tc<true, false><<<dim3(DFF_ / 128, ROWS_ / 128), thr, GEMM_SMEM>>>(h, W1, b1, nullptr, hid, DFF_, D_);

    // 8) FFN2 + residual (x1) -> output
    gemm_tc<false, true><<<dim3(D_ / 128, ROWS_ / 128), thr, GEMM_SMEM>>>(hid, W2, b2, x1, out, D_, DFF_);
}

// round 12
// speedup vs baseline: 2.6495x; 1.0401x over previous
#include <cuda_runtime.h>

// ---------------------------------------------------------------------------
// Problem constants (fixed shapes)
// ---------------------------------------------------------------------------
namespace {
constexpr int B_    = 2;
constexpr int T_    = 12;
constexpr int N_    = 512;     // nodes
constexpr int D_    = 512;     // model dim
constexpr int KH_   = 8;       // heads
constexpr int DH_   = 64;      // head dim
constexpr int DFF_  = 2048;    // ffn hidden
constexpr int BT_   = B_ * T_;         // 24
constexpr int ROWS_ = BT_ * N_;        // 12288 token rows

// gemm: 3-stage cp.async pipeline, A/B tiles [128][36] fp32
constexpr int GEMM_TILE   = 128 * 36;                       // floats per tile
constexpr int GEMM_SMEM   = 3 * 2 * GEMM_TILE * 4;          // 110592 B

// attention smem (floats), 64 queries per block:
//   Qs 64x68 (tf32) | S 64x517 (fp32 logits -> tf32 probs; reused for partials)
//   ST 256x68 (K stage; also Vt 64x261 stage)
constexpr int ATT_Q_   = 64 * 68;       // 4352
constexpr int ATT_S_   = 64 * 517;      // 33088
constexpr int ATT_ST_  = 256 * 68;      // 17408  (Vt 64x261 = 16704 fits)
constexpr int ATT_SMEM = (ATT_Q_ + ATT_S_ + ATT_ST_) * 4;   // 219392 B
}

// ---------------------------------------------------------------------------
// Scratch (static device globals: the sanctioned alloc-free scratch path)
// ---------------------------------------------------------------------------
__device__ __align__(16) float g_xn [ROWS_ * D_];
__device__ __align__(16) float g_q  [ROWS_ * D_];
__device__ __align__(16) float g_k  [ROWS_ * D_];
__device__ __align__(16) float g_v  [ROWS_ * D_];
__device__ __align__(16) float g_ao [ROWS_ * D_];
__device__ __align__(16) float g_x1 [ROWS_ * D_];
__device__ __align__(16) float g_h  [ROWS_ * D_];
__device__ __align__(16) float g_hid[ROWS_ * DFF_];
__device__ __align__(16) float g_bias[N_ * N_];

// ---------------------------------------------------------------------------
// helpers
// ---------------------------------------------------------------------------
__device__ __forceinline__ unsigned f2tf32(float x) {
    unsigned r;
    asm("cvt.rna.tf32.f32 %0, %1;" : "=r"(r) : "f"(x));
    return r;
}
__device__ __forceinline__ void cp16(unsigned dst, const void* src) {
    asm volatile("cp.async.cg.shared.global [%0], [%1], 16;\n" :: "r"(dst), "l"(src));
}
#define MMA_TF32(acc, af, bf)                                                  \
    asm volatile(                                                              \
        "mma.sync.aligned.m16n8k8.row.col.f32.tf32.tf32.f32 "                  \
        "{%0,%1,%2,%3}, {%4,%5,%6,%7}, {%8,%9}, {%0,%1,%2,%3};\n"              \
        : "+f"((acc)[0]), "+f"((acc)[1]), "+f"((acc)[2]), "+f"((acc)[3])       \
        : "r"((af)[0]), "r"((af)[1]), "r"((af)[2]), "r"((af)[3]),              \
          "r"((bf)[0]), "r"((bf)[1]))

// ---------------------------------------------------------------------------
// Kernel 1: graph bias  bias[n][m] = a*softmax_row(relu(En.Em)) + b*lap + mask
// ---------------------------------------------------------------------------
__global__ void bias_kernel(const float* __restrict__ E,
                            const float* __restrict__ lap,
                            const float* __restrict__ alphap,
                            const float* __restrict__ betap,
                            float* __restrict__ bias) {
    __shared__ float en[64];
    __shared__ float red[512];
    const int n = blockIdx.x;
    const int t = threadIdx.x;

    if (t < 64) en[t] = E[n * 64 + t];
    __syncthreads();

    const float* em = E + t * 64;
    float acc = 0.f;
#pragma unroll 16
    for (int j = 0; j < 64; j++) acc = fmaf(en[j], em[j], acc);
    float r = fmaxf(acc, 0.f);

    red[t] = r;
    __syncthreads();
    for (int s = 256; s > 0; s >>= 1) {
        if (t < s) red[t] = fmaxf(red[t], red[t + s]);
        __syncthreads();
    }
    const float mx = red[0];
    __syncthreads();

    const float e = __expf(r - mx);
    red[t] = e;
    __syncthreads();
    for (int s = 256; s > 0; s >>= 1) {
        if (t < s) red[t] += red[t + s];
        __syncthreads();
    }
    const float soft = e / red[0];

    const float lv   = lap[n * N_ + t];
    const float mask = (lv == 0.f) ? -1e9f : 0.f;
    bias[n * N_ + t] = (*alphap) * soft + (*betap) * lv + mask;
}

// ---------------------------------------------------------------------------
// Kernel 2: LayerNorm over last dim (512). one block (128 thr) per row.
// ---------------------------------------------------------------------------
__global__ void ln_kernel(const float* __restrict__ x,
                          const float* __restrict__ g,
                          const float* __restrict__ be,
                          float* __restrict__ y) {
    const int row = blockIdx.x;
    const int t   = threadIdx.x;  // 128
    const float4 v = ((const float4*)(x + (size_t)row * D_))[t];

    float s  = v.x + v.y + v.z + v.w;
    float ss = fmaf(v.x, v.x, fmaf(v.y, v.y, fmaf(v.z, v.z, v.w * v.w)));
#pragma unroll
    for (int o = 16; o; o >>= 1) {
        s  += __shfl_xor_sync(0xffffffffu, s,  o);
        ss += __shfl_xor_sync(0xffffffffu, ss, o);
    }
    __shared__ float sh_s[4], sh_ss[4];
    const int warp = t >> 5, lane = t & 31;
    if (lane == 0) { sh_s[warp] = s; sh_ss[warp] = ss; }
    __syncthreads();
    const float ts  = sh_s[0] + sh_s[1] + sh_s[2] + sh_s[3];
    const float tss = sh_ss[0] + sh_ss[1] + sh_ss[2] + sh_ss[3];

    const float mean = ts * (1.f / 512.f);
    const float var  = tss * (1.f / 512.f) - mean * mean;
    const float inv  = rsqrtf(var + 1e-5f);

    const float4 gv = ((const float4*)g)[t];
    const float4 bv = ((const float4*)be)[t];
    float4 o;
    o.x = (v.x - mean) * inv * gv.x + bv.x;
    o.y = (v.y - mean) * inv * gv.y + bv.y;
    o.z = (v.z - mean) * inv * gv.z + bv.z;
    o.w = (v.w - mean) * inv * gv.w + bv.w;
    ((float4*)(y + (size_t)row * D_))[t] = o;
}

// ---------------------------------------------------------------------------
// GEMM body: TF32 tensor-core GEMM NT, cp.async 3-stage pipeline,
// register-level fragment double buffering.
// C[M,Nc] = A[M,Kc] @ W[Nc,Kc]^T (+bias)(+res)(relu)
// 128x128 block tile, BK=32, 256 threads / 8 warps, warp tile 32x64.
// ---------------------------------------------------------------------------
__device__ __forceinline__ void load_frags(const unsigned* __restrict__ Ab,
                                           const unsigned* __restrict__ Bb,
                                           int wm, int wn, int gid, int t4, int ks,
                                           unsigned af[2][4], unsigned bf[8][2]) {
#pragma unroll
    for (int i = 0; i < 2; i++) {
        const unsigned* p = Ab + (wm + 16 * i + gid) * 36 + ks * 8 + t4;
        af[i][0] = p[0]; af[i][1] = p[8 * 36]; af[i][2] = p[4]; af[i][3] = p[8 * 36 + 4];
    }
#pragma unroll
    for (int j = 0; j < 8; j++) {
        const unsigned* p = Bb + (wn + 8 * j + gid) * 36 + ks * 8 + t4;
        bf[j][0] = p[0]; bf[j][1] = p[4];
    }
}

template <bool RELU, bool HAS_RES>
__device__ __forceinline__
void gemm_body(const float* __restrict__ A, const float* __restrict__ W,
               const float* __restrict__ bias, const float* __restrict__ res,
               float* __restrict__ C, int Nc, int Kc, float* smf) {
    const int tid  = threadIdx.x;
    const int warp = tid >> 5, lane = tid & 31;
    const int gid  = lane >> 2, t4 = lane & 3;
    const int wm   = (warp & 3) * 32;
    const int wn   = (warp >> 2) * 64;
    const int bm   = blockIdx.y * 128;
    const int bn   = blockIdx.x * 128;
    const int lr   = tid >> 1;          // 0..127
    const int lc   = (tid & 1) * 16;    // 0 or 16 (float index)

    const float* Ap = A + (size_t)(bm + lr) * Kc + lc;
    const float* Wp = W + (size_t)(bn + lr) * Kc + lc;
    const unsigned sbase = (unsigned)__cvta_generic_to_shared(smf);
    const unsigned soff  = (unsigned)(lr * 36 + lc) * 4u;
    const int stages = Kc >> 5;

    float acc[2][8][4];
#pragma unroll
    for (int i = 0; i < 2; i++)
#pragma unroll
        for (int j = 0; j < 8; j++)
#pragma unroll
            for (int c = 0; c < 4; c++) acc[i][j][c] = 0.f;

    // prologue: stages 0,1
#pragma unroll
    for (int s = 0; s < 2; s++) {
        const unsigned da = sbase + (unsigned)(s * 2 * GEMM_TILE) * 4u + soff;
        const unsigned db = da + (unsigned)GEMM_TILE * 4u;
        const float* a = Ap + s * 32;
        const float* w = Wp + s * 32;
#pragma unroll
        for (int e = 0; e < 4; e++) { cp16(da + e * 16, a + e * 4); cp16(db + e * 16, w + e * 4); }
        asm volatile("cp.async.commit_group;\n");
    }

    for (int s = 0; s < stages; s++) {
        if (s + 1 < stages) asm volatile("cp.async.wait_group 1;\n");
        else                asm volatile("cp.async.wait_group 0;\n");
        __syncthreads();

        if (s + 2 < stages) {
            const int sn = s + 2;
            const unsigned da = sbase + (unsigned)((sn % 3) * 2 * GEMM_TILE) * 4u + soff;
            const unsigned db = da + (unsigned)GEMM_TILE * 4u;
            const float* a = Ap + sn * 32;
            const float* w = Wp + sn * 32;
#pragma unroll
            for (int e = 0; e < 4; e++) { cp16(da + e * 16, a + e * 4); cp16(db + e * 16, w + e * 4); }
            asm volatile("cp.async.commit_group;\n");
        }

        const unsigned* Ab = (const unsigned*)(smf + (s % 3) * 2 * GEMM_TILE);
        const unsigned* Bb = Ab + GEMM_TILE;

        // fragment double buffering across the 4 k8 steps
        unsigned af[2][2][4], bf[2][8][2];
        load_frags(Ab, Bb, wm, wn, gid, t4, 0, af[0], bf[0]);
#pragma unroll
        for (int ks = 0; ks < 4; ks++) {
            if (ks < 3)
                load_frags(Ab, Bb, wm, wn, gid, t4, ks + 1, af[(ks + 1) & 1], bf[(ks + 1) & 1]);
            const int cur = ks & 1;
#pragma unroll
            for (int i = 0; i < 2; i++)
#pragma unroll
                for (int j = 0; j < 8; j++) MMA_TF32(acc[i][j], af[cur][i], bf[cur][j]);
        }
    }

    // epilogue
#pragma unroll
    for (int i = 0; i < 2; i++) {
        const int r0 = bm + wm + 16 * i + gid;
#pragma unroll
        for (int j = 0; j < 8; j++) {
            const int col = bn + wn + 8 * j + 2 * t4;
            const float2 bv = *(const float2*)(bias + col);
            float o00 = acc[i][j][0] + bv.x;
            float o01 = acc[i][j][1] + bv.y;
            float o10 = acc[i][j][2] + bv.x;
            float o11 = acc[i][j][3] + bv.y;
            if (HAS_RES) {
                const float2 rv0 = *(const float2*)(res + (size_t)r0 * Nc + col);
                const float2 rv1 = *(const float2*)(res + (size_t)(r0 + 8) * Nc + col);
                o00 += rv0.x; o01 += rv0.y;
                o10 += rv1.x; o11 += rv1.y;
            }
            if (RELU) {
                o00 = fmaxf(o00, 0.f); o01 = fmaxf(o01, 0.f);
                o10 = fmaxf(o10, 0.f); o11 = fmaxf(o11, 0.f);
            }
            *(float2*)(C + (size_t)r0 * Nc + col)       = make_float2(o00, o01);
            *(float2*)(C + (size_t)(r0 + 8) * Nc + col) = make_float2(o10, o11);
        }
    }
}

template <bool RELU, bool HAS_RES>
__global__ __launch_bounds__(256, 2)
void gemm_tc(const float* __restrict__ A, const float* __restrict__ W,
             const float* __restrict__ bias, const float* __restrict__ res,
             float* __restrict__ C, int Nc, int Kc) {
    extern __shared__ float smf[];
    gemm_body<RELU, HAS_RES>(A, W, bias, res, C, Nc, Kc, smf);
}

// fused QKV: blockIdx.z selects weight/bias/output (shared A, one launch)
struct QKVArgs {
    const float* W[3];
    const float* b[3];
    float*       o[3];
};
__global__ __launch_bounds__(256, 2)
void gemm_qkv(const float* __restrict__ A, QKVArgs args) {
    extern __shared__ float smf[];
    const int z = blockIdx.z;
    gemm_body<false, false>(A, args.W[z], args.b[z], nullptr, args.o[z], D_, D_, smf);
}

// ---------------------------------------------------------------------------
// Kernel 4: tensor-core attention. block = (head, 64-query tile), 256 thr.
// Phase1: S = Q K^T * scale + bias via tf32 mma; K cp.async-staged in
//         256-key chunks; 8 warps = 2(M) x 4(N) grid of 32x64 warp tiles
//         (1.5 LDS/MMA, gemm-grade).
// Phase2: exact row softmax in smem; P rewritten RNA-rounded tf32.
// Phase3: O = P V; Vt staged transposed per 256-key chunk; warp =
//         (query-half, 64-key split); partials reduced through smem.
// ---------------------------------------------------------------------------
__global__ __launch_bounds__(256)
void attn_tc(const float* __restrict__ Q, const float* __restrict__ Kx,
             const float* __restrict__ V, const float* __restrict__ bias,
             float* __restrict__ O) {
    extern __shared__ float sm[];
    float*    Qs  = sm;                 // 64 x 68 (tf32 bits, scaled)
    float*    S   = sm + ATT_Q_;        // 64 x 517 (fp32 -> tf32 probs -> partials)
    float*    ST  = S + ATT_S_;         // K: 256x68 / Vt: 64x261
    unsigned* Qu  = (unsigned*)Qs;
    unsigned* Su  = (unsigned*)S;
    unsigned* STu = (unsigned*)ST;

    const int tid  = threadIdx.x;
    const int warp = tid >> 5, lane = tid & 31;
    const int gid  = lane >> 2, t4 = lane & 3;
    const int hidx = blockIdx.y;        // 0..191
    const int bt   = hidx >> 3;
    const int kh   = hidx & 7;
    const int n0   = blockIdx.x * 64;
    const size_t rowbase = (size_t)bt * N_;
    const size_t headoff = (size_t)kh * DH_;
    const unsigned stbase = (unsigned)__cvta_generic_to_shared(ST);

    // load Q tile (64 x 64), scale by 1/sqrt(64)=0.125, RNA->tf32
    for (int i = tid; i < 64 * 16; i += 256) {
        const int r = i >> 4, c = (i & 15) << 2;
        const float4 vv = *(const float4*)(Q + (rowbase + n0 + r) * D_ + headoff + c);
        unsigned* qd = Qu + r * 68 + c;
        qd[0] = f2tf32(vv.x * 0.125f); qd[1] = f2tf32(vv.y * 0.125f);
        qd[2] = f2tf32(vv.z * 0.125f); qd[3] = f2tf32(vv.w * 0.125f);
    }

    // ---- phase 1: S = Q K^T + bias (2 chunks of 256 keys) ----------------
    const int wq = (warp & 1) * 32;     // query tile base
    const int wk = (warp >> 1) * 64;    // key base within chunk
    for (int ch = 0; ch < 2; ch++) {
        const int m0 = ch * 256;
        __syncthreads();
        // cp.async K chunk (raw fp32; tensor core truncates to tf32)
        for (int i = tid; i < 256 * 4; i += 256) {
            const int r = i >> 2, c = (i & 3) << 4;
            const unsigned dst = stbase + (unsigned)(r * 68 + c) * 4u;
            const float* src = Kx + (rowbase + m0 + r) * D_ + headoff + c;
            cp16(dst,      src);
            cp16(dst + 16, src + 4);
            cp16(dst + 32, src + 8);
            cp16(dst + 48, src + 12);
        }
        asm volatile("cp.async.commit_group;\n");
        asm volatile("cp.async.wait_group 0;\n");
        __syncthreads();

        float acc[2][8][4];
#pragma unroll
        for (int i = 0; i < 2; i++)
#pragma unroll
            for (int j = 0; j < 8; j++)
#pragma unroll
                for (int c = 0; c < 4; c++) acc[i][j][c] = 0.f;

#pragma unroll
        for (int ks = 0; ks < 8; ks++) {
            unsigned af[2][4], bf[8][2];
#pragma unroll
            for (int i = 0; i < 2; i++) {
                const unsigned* p = Qu + (wq + 16 * i + gid) * 68 + ks * 8 + t4;
                af[i][0] = p[0]; af[i][1] = p[8 * 68]; af[i][2] = p[4]; af[i][3] = p[8 * 68 + 4];
            }
#pragma unroll
            for (int j = 0; j < 8; j++) {
                const unsigned* p = STu + (wk + 8 * j + gid) * 68 + ks * 8 + t4;
                bf[j][0] = p[0]; bf[j][1] = p[4];
            }
#pragma unroll
            for (int i = 0; i < 2; i++)
#pragma unroll
                for (int j = 0; j < 8; j++) MMA_TF32(acc[i][j], af[i], bf[j]);
        }

        // store S (+bias)
#pragma unroll
        for (int i = 0; i < 2; i++) {
            const int r0 = wq + 16 * i + gid;
#pragma unroll
            for (int j = 0; j < 8; j++) {
                const int col = wk + 8 * j + 2 * t4;      // within chunk
                const float2 b0 = *(const float2*)(bias + (size_t)(n0 + r0) * N_ + m0 + col);
                const float2 b1 = *(const float2*)(bias + (size_t)(n0 + r0 + 8) * N_ + m0 + col);
                S[r0 * 517 + m0 + col]           = acc[i][j][0] + b0.x;
                S[r0 * 517 + m0 + col + 1]       = acc[i][j][1] + b0.y;
                S[(r0 + 8) * 517 + m0 + col]     = acc[i][j][2] + b1.x;
                S[(r0 + 8) * 517 + m0 + col + 1] = acc[i][j][3] + b1.y;
            }
        }
    }
    __syncthreads();

    // ---- phase 2: exact row softmax; rewrite P as RNA tf32 ---------------
    {
#pragma unroll
        for (int ii = 0; ii < 8; ii++) {
            float*    row  = S  + (warp * 8 + ii) * 517;
            unsigned* rowu = Su + (warp * 8 + ii) * 517;
            float mx = -3.4e38f;
            for (int m = lane; m < N_; m += 32) mx = fmaxf(mx, row[m]);
#pragma unroll
            for (int o = 16; o; o >>= 1) mx = fmaxf(mx, __shfl_xor_sync(0xffffffffu, mx, o));
            float sum = 0.f;
            for (int m = lane; m < N_; m += 32) {
                const float e = __expf(row[m] - mx);
                row[m] = e;
                sum += e;
            }
#pragma unroll
            for (int o = 16; o; o >>= 1) sum += __shfl_xor_sync(0xffffffffu, sum, o);
            const float inv = 1.f / sum;
            for (int m = lane; m < N_; m += 32) rowu[m] = f2tf32(row[m] * inv);
        }
    }

    // ---- phase 3: O = P V. warp = (query-half, 64-key split of chunk) ----
    const int wq3 = (warp & 1) * 32;    // query tile base
    const int kg  = warp >> 1;          // 0..3: 64-key group within chunk
    float acc3[2][8][4];
#pragma unroll
    for (int i = 0; i < 2; i++)
#pragma unroll
        for (int j = 0; j < 8; j++)
#pragma unroll
            for (int c = 0; c < 4; c++) acc3[i][j][c] = 0.f;

    for (int ch = 0; ch < 2; ch++) {
        const int m0 = ch * 256;
        __syncthreads();
        // stage Vt[d][m] (transposed, RNA->tf32), stride 261
        for (int i = tid; i < 256 * 16; i += 256) {
            const int r = i >> 4, c = (i & 15) << 2;   // r = key, c = d
            const float4 vv = *(const float4*)(V + (rowbase + m0 + r) * D_ + headoff + c);
            STu[(c + 0) * 261 + r] = f2tf32(vv.x);
            STu[(c + 1) * 261 + r] = f2tf32(vv.y);
            STu[(c + 2) * 261 + r] = f2tf32(vv.z);
            STu[(c + 3) * 261 + r] = f2tf32(vv.w);
        }
        __syncthreads();

#pragma unroll
        for (int ks = 0; ks < 8; ks++) {
            unsigned af[2][4], bf[8][2];
#pragma unroll
            for (int i = 0; i < 2; i++) {
                const unsigned* p = Su + (wq3 + 16 * i + gid) * 517 + m0 + kg * 64 + ks * 8 + t4;
                af[i][0] = p[0]; af[i][1] = p[8 * 517]; af[i][2] = p[4]; af[i][3] = p[8 * 517 + 4];
            }
#pragma unroll
            for (int j = 0; j < 8; j++) {
                const unsigned* p = STu + (8 * j + gid) * 261 + kg * 64 + ks * 8 + t4;
                bf[j][0] = p[0]; bf[j][1] = p[4];
            }
#pragma unroll
            for (int i = 0; i < 2; i++)
#pragma unroll
                for (int j = 0; j < 8; j++) MMA_TF32(acc3[i][j], af[i], bf[j]);
        }
    }

    // reduce the 4 k-split partials through smem (reuse S region, stride 68)
    __syncthreads();
    {
        float* part = S + warp * (32 * 68);
#pragma unroll
        for (int i = 0; i < 2; i++) {
            const int r = 16 * i + gid;
#pragma unroll
            for (int j = 0; j < 8; j++) {
                const int c = 8 * j + 2 * t4;
                *(float2*)(part + r * 68 + c)       = make_float2(acc3[i][j][0], acc3[i][j][1]);
                *(float2*)(part + (r + 8) * 68 + c) = make_float2(acc3[i][j][2], acc3[i][j][3]);
            }
        }
    }
    __syncthreads();

    // sum over kg and write O
    for (int i = tid; i < 64 * 16; i += 256) {
        const int q  = i >> 4, dc = (i & 15) << 2;
        const int mt = q >> 5, qi = q & 31;
        float4 o = make_float4(0.f, 0.f, 0.f, 0.f);
#pragma unroll
        for (int kg2 = 0; kg2 < 4; kg2++) {
            const float4 p = *(const float4*)(S + (kg2 * 2 + mt) * (32 * 68) + qi * 68 + dc);
            o.x += p.x; o.y += p.y; o.z += p.z; o.w += p.w;
        }
        *(float4*)(O + (rowbase + n0 + q) * D_ + headoff + dc) = o;
    }
}

// ---------------------------------------------------------------------------
// Launch
// ---------------------------------------------------------------------------
extern "C" void kernel_launch(void* const* d_in, const int* in_sizes, int n_in,
                              void* d_out, int out_size) {
    (void)in_sizes; (void)n_in; (void)out_size;
    const float* x    = (const float*)d_in[0];
    const float* lap  = (const float*)d_in[1];
    const float* ne   = (const float*)d_in[2];
    const float* Wq   = (const float*)d_in[3];
    const float* bq   = (const float*)d_in[4];
    const float* Wk   = (const float*)d_in[5];
    const float* bk   = (const float*)d_in[6];
    const float* Wv   = (const float*)d_in[7];
    const float* bv   = (const float*)d_in[8];
    const float* Wo   = (const float*)d_in[9];
    const float* bo   = (const float*)d_in[10];
    const float* W1   = (const float*)d_in[11];
    const float* b1   = (const float*)d_in[12];
    const float* W2   = (const float*)d_in[13];
    const float* b2   = (const float*)d_in[14];
    const float* g1   = (const float*)d_in[15];
    const float* be1  = (const float*)d_in[16];
    const float* g2   = (const float*)d_in[17];
    const float* be2  = (const float*)d_in[18];
    const float* alp  = (const float*)d_in[19];
    const float* bet  = (const float*)d_in[20];
    float* out = (float*)d_out;

    float *xn, *q, *k, *v, *ao, *x1, *h, *hid, *bias;
    cudaGetSymbolAddress((void**)&xn,   g_xn);
    cudaGetSymbolAddress((void**)&q,    g_q);
    cudaGetSymbolAddress((void**)&k,    g_k);
    cudaGetSymbolAddress((void**)&v,    g_v);
    cudaGetSymbolAddress((void**)&ao,   g_ao);
    cudaGetSymbolAddress((void**)&x1,   g_x1);
    cudaGetSymbolAddress((void**)&h,    g_h);
    cudaGetSymbolAddress((void**)&hid,  g_hid);
    cudaGetSymbolAddress((void**)&bias, g_bias);

    cudaFuncSetAttribute(attn_tc,
                         cudaFuncAttributeMaxDynamicSharedMemorySize, ATT_SMEM);
    cudaFuncSetAttribute(gemm_qkv,
                         cudaFuncAttributeMaxDynamicSharedMemorySize, GEMM_SMEM);
    cudaFuncSetAttribute(gemm_tc<false, false>,
                         cudaFuncAttributeMaxDynamicSharedMemorySize, GEMM_SMEM);
    cudaFuncSetAttribute(gemm_tc<false, true>,
                         cudaFuncAttributeMaxDynamicSharedMemorySize, GEMM_SMEM);
    cudaFuncSetAttribute(gemm_tc<true, false>,
                         cudaFuncAttributeMaxDynamicSharedMemorySize, GEMM_SMEM);

    // 1) graph bias (b,t,k-invariant)
    bias_kernel<<<N_, N_>>>(ne, lap, alp, bet, bias);

    // 2) LN1
    ln_kernel<<<ROWS_, 128>>>(x, g1, be1, xn);

    // 3) Q/K/V projections — fused single launch (shared A, 3x L2 reuse)
    const dim3 thr(256);
    QKVArgs qa;
    qa.W[0] = Wq; qa.W[1] = Wk; qa.W[2] = Wv;
    qa.b[0] = bq; qa.b[1] = bk; qa.b[2] = bv;
    qa.o[0] = q;  qa.o[1] = k;  qa.o[2] = v;
    gemm_qkv<<<dim3(D_ / 128, ROWS_ / 128, 3), thr, GEMM_SMEM>>>(xn, qa);

    // 4) attention (192 heads x 8 query tiles, tensor cores)
    attn_tc<<<dim3(N_ / 64, BT_ * KH_), thr, ATT_SMEM>>>(q, k, v, bias, ao);

    // 5) output projection + residual (x)
    gemm_tc<false, true><<<dim3(D_ / 128, ROWS_ / 128), thr, GEMM_SMEM>>>(ao, Wo, bo, x, x1, D_, D_);

    // 6) LN2
    ln_kernel<<<ROWS_, 128>>>(x1, g2, be2, h);

    // 7) FFN1 with fused ReLU
    gemm_tc<true, false><<<dim3(DFF_ / 128, ROWS_ / 128), thr, GEMM_SMEM>>>(h, W1, b1, nullptr, hid, DFF_, D_);

    // 8) FFN2 + residual (x1) -> output
    gemm_tc<false, true><<<dim3(D_ / 128, ROWS_ / 128), thr, GEMM_SMEM>>>(hid, W2, b2, x1, out, D_, DFF_);
}

// round 15
// speedup vs baseline: 3.7913x; 1.4309x over previous
#include <cuda_runtime.h>
#include <cuda_fp16.h>

// ---------------------------------------------------------------------------
// Problem constants (fixed shapes)
// ---------------------------------------------------------------------------
namespace {
constexpr int B_    = 2;
constexpr int T_    = 12;
constexpr int N_    = 512;     // nodes
constexpr int D_    = 512;     // model dim
constexpr int KH_   = 8;       // heads
constexpr int DH_   = 64;      // head dim
constexpr int DFF_  = 2048;    // ffn hidden
constexpr int BT_   = B_ * T_;         // 24
constexpr int ROWS_ = BT_ * N_;        // 12288 token rows

// fp16 gemm: BK=64 halves (128 B/row), padded row = 36 words (72 halves)
constexpr int GEMM_TILE   = 128 * 36;                       // words per tile
constexpr int GEMM_SMEM   = 3 * 2 * GEMM_TILE * 4;          // 110592 B

// attention smem (floats), 64 queries per block (unchanged from R12)
constexpr int ATT_Q_   = 64 * 68;       // 4352
constexpr int ATT_S_   = 64 * 517;      // 33088
constexpr int ATT_ST_  = 256 * 68;      // 17408  (Vt 64x261 = 16704 fits)
constexpr int ATT_SMEM = (ATT_Q_ + ATT_S_ + ATT_ST_) * 4;   // 219392 B
}

// ---------------------------------------------------------------------------
// Scratch (static device globals: the sanctioned alloc-free scratch path)
// ---------------------------------------------------------------------------
__device__ __align__(16) float  g_q   [ROWS_ * D_];
__device__ __align__(16) float  g_k   [ROWS_ * D_];
__device__ __align__(16) float  g_v   [ROWS_ * D_];
__device__ __align__(16) float  g_x1  [ROWS_ * D_];
__device__ __align__(16) float  g_bias[N_ * N_];
__device__ __align__(16) __half g_xnh [ROWS_ * D_];
__device__ __align__(16) __half g_hh  [ROWS_ * D_];
__device__ __align__(16) __half g_aoh [ROWS_ * D_];
__device__ __align__(16) __half g_hidh[ROWS_ * DFF_];
__device__ __align__(16) __half g_wqh [D_ * D_];
__device__ __align__(16) __half g_wkh [D_ * D_];
__device__ __align__(16) __half g_wvh [D_ * D_];
__device__ __align__(16) __half g_woh [D_ * D_];
__device__ __align__(16) __half g_w1h [DFF_ * D_];
__device__ __align__(16) __half g_w2h [D_ * DFF_];

// ---------------------------------------------------------------------------
// helpers
// ---------------------------------------------------------------------------
__device__ __forceinline__ unsigned f2tf32(float x) {
    unsigned r;
    asm("cvt.rna.tf32.f32 %0, %1;" : "=r"(r) : "f"(x));
    return r;
}
__device__ __forceinline__ void cp16(unsigned dst, const void* src) {
    asm volatile("cp.async.cg.shared.global [%0], [%1], 16;\n" :: "r"(dst), "l"(src));
}
#define MMA_TF32(acc, af, bf)                                                  \
    asm volatile(                                                              \
        "mma.sync.aligned.m16n8k8.row.col.f32.tf32.tf32.f32 "                  \
        "{%0,%1,%2,%3}, {%4,%5,%6,%7}, {%8,%9}, {%0,%1,%2,%3};\n"              \
        : "+f"((acc)[0]), "+f"((acc)[1]), "+f"((acc)[2]), "+f"((acc)[3])       \
        : "r"((af)[0]), "r"((af)[1]), "r"((af)[2]), "r"((af)[3]),              \
          "r"((bf)[0]), "r"((bf)[1]))
#define MMA_F16(acc, af, bf)                                                   \
    asm volatile(                                                              \
        "mma.sync.aligned.m16n8k16.row.col.f32.f16.f16.f32 "                   \
        "{%0,%1,%2,%3}, {%4,%5,%6,%7}, {%8,%9}, {%0,%1,%2,%3};\n"              \
        : "+f"((acc)[0]), "+f"((acc)[1]), "+f"((acc)[2]), "+f"((acc)[3])       \
        : "r"((af)[0]), "r"((af)[1]), "r"((af)[2]), "r"((af)[3]),              \
          "r"((bf)[0]), "r"((bf)[1]))

// ---------------------------------------------------------------------------
// Kernel 0: fp32 -> fp16 conversion (weights), vectorized, grid-stride
// ---------------------------------------------------------------------------
__global__ void cvt_f2h(const float* __restrict__ s, __half* __restrict__ d, int n4) {
    for (int i = blockIdx.x * blockDim.x + threadIdx.x; i < n4;
         i += gridDim.x * blockDim.x) {
        const float4 v = ((const float4*)s)[i];
        __half2* dp = (__half2*)d + 2 * i;
        dp[0] = __floats2half2_rn(v.x, v.y);
        dp[1] = __floats2half2_rn(v.z, v.w);
    }
}

// ---------------------------------------------------------------------------
// Kernel 1: graph bias  bias[n][m] = a*softmax_row(relu(En.Em)) + b*lap + mask
// ---------------------------------------------------------------------------
__global__ void bias_kernel(const float* __restrict__ E,
                            const float* __restrict__ lap,
                            const float* __restrict__ alphap,
                            const float* __restrict__ betap,
                            float* __restrict__ bias) {
    __shared__ float en[64];
    __shared__ float red[512];
    const int n = blockIdx.x;
    const int t = threadIdx.x;

    if (t < 64) en[t] = E[n * 64 + t];
    __syncthreads();

    const float* em = E + t * 64;
    float acc = 0.f;
#pragma unroll 16
    for (int j = 0; j < 64; j++) acc = fmaf(en[j], em[j], acc);
    float r = fmaxf(acc, 0.f);

    red[t] = r;
    __syncthreads();
    for (int s = 256; s > 0; s >>= 1) {
        if (t < s) red[t] = fmaxf(red[t], red[t + s]);
        __syncthreads();
    }
    const float mx = red[0];
    __syncthreads();

    const float e = __expf(r - mx);
    red[t] = e;
    __syncthreads();
    for (int s = 256; s > 0; s >>= 1) {
        if (t < s) red[t] += red[t + s];
        __syncthreads();
    }
    const float soft = e / red[0];

    const float lv   = lap[n * N_ + t];
    const float mask = (lv == 0.f) ? -1e9f : 0.f;
    bias[n * N_ + t] = (*alphap) * soft + (*betap) * lv + mask;
}

// ---------------------------------------------------------------------------
// Kernel 2: LayerNorm over last dim (512), fp16 output. 128 thr per row.
// ---------------------------------------------------------------------------
__global__ void ln_kernel(const float* __restrict__ x,
                          const float* __restrict__ g,
                          const float* __restrict__ be,
                          __half* __restrict__ y) {
    const int row = blockIdx.x;
    const int t   = threadIdx.x;  // 128
    const float4 v = ((const float4*)(x + (size_t)row * D_))[t];

    float s  = v.x + v.y + v.z + v.w;
    float ss = fmaf(v.x, v.x, fmaf(v.y, v.y, fmaf(v.z, v.z, v.w * v.w)));
#pragma unroll
    for (int o = 16; o; o >>= 1) {
        s  += __shfl_xor_sync(0xffffffffu, s,  o);
        ss += __shfl_xor_sync(0xffffffffu, ss, o);
    }
    __shared__ float sh_s[4], sh_ss[4];
    const int warp = t >> 5, lane = t & 31;
    if (lane == 0) { sh_s[warp] = s; sh_ss[warp] = ss; }
    __syncthreads();
    const float ts  = sh_s[0] + sh_s[1] + sh_s[2] + sh_s[3];
    const float tss = sh_ss[0] + sh_ss[1] + sh_ss[2] + sh_ss[3];

    const float mean = ts * (1.f / 512.f);
    const float var  = tss * (1.f / 512.f) - mean * mean;
    const float inv  = rsqrtf(var + 1e-5f);

    const float4 gv = ((const float4*)g)[t];
    const float4 bv = ((const float4*)be)[t];
    float4 o;
    o.x = (v.x - mean) * inv * gv.x + bv.x;
    o.y = (v.y - mean) * inv * gv.y + bv.y;
    o.z = (v.z - mean) * inv * gv.z + bv.z;
    o.w = (v.w - mean) * inv * gv.w + bv.w;
    __half2* yp = (__half2*)(y + (size_t)row * D_) + t * 2;
    yp[0] = __floats2half2_rn(o.x, o.y);
    yp[1] = __floats2half2_rn(o.z, o.w);
}

// ---------------------------------------------------------------------------
// FP16 tensor-core GEMM NT: C[M,Nc] = A[M,Kc] @ W[Nc,Kc]^T (+bias)(+res)(relu)
// A, W fp16; fp32 accumulate. 128x128 block tile, BK=64 halves, 256 thr /
// 8 warps, warp tile 32x64, cp.async 3-stage pipeline + frag double buffer.
// Word-level smem indexing identical to the verified tf32 kernel (each .b32
// carries 2 halves; mma is m16n8k16).
// ---------------------------------------------------------------------------
__device__ __forceinline__ void load_frags(const unsigned* __restrict__ Ab,
                                           const unsigned* __restrict__ Bb,
                                           int wm, int wn, int gid, int t4, int ks,
                                           unsigned af[2][4], unsigned bf[8][2]) {
#pragma unroll
    for (int i = 0; i < 2; i++) {
        const unsigned* p = Ab + (wm + 16 * i + gid) * 36 + ks * 8 + t4;
        af[i][0] = p[0]; af[i][1] = p[8 * 36]; af[i][2] = p[4]; af[i][3] = p[8 * 36 + 4];
    }
#pragma unroll
    for (int j = 0; j < 8; j++) {
        const unsigned* p = Bb + (wn + 8 * j + gid) * 36 + ks * 8 + t4;
        bf[j][0] = p[0]; bf[j][1] = p[4];
    }
}

template <bool RELU, bool HAS_RES, bool OUTH>
__device__ __forceinline__
void gemm_body(const __half* __restrict__ A, const __half* __restrict__ W,
               const float* __restrict__ bias, const float* __restrict__ res,
               void* __restrict__ Cv, int Nc, int Kc, float* smf) {
    const int tid  = threadIdx.x;
    const int warp = tid >> 5, lane = tid & 31;
    const int gid  = lane >> 2, t4 = lane & 3;
    const int wm   = (warp & 3) * 32;
    const int wn   = (warp >> 2) * 64;
    const int bm   = blockIdx.y * 128;
    const int bn   = blockIdx.x * 128;
    const int lr   = tid >> 1;          // 0..127
    const int lch  = (tid & 1) * 32;    // 0 or 32 (half index)

    const __half* Ap = A + (size_t)(bm + lr) * Kc + lch;
    const __half* Wp = W + (size_t)(bn + lr) * Kc + lch;
    const unsigned sbase = (unsigned)__cvta_generic_to_shared(smf);
    const unsigned soff  = (unsigned)(lr * 36 + (tid & 1) * 16) * 4u;  // bytes
    const int stages = Kc >> 6;

    float acc[2][8][4];
#pragma unroll
    for (int i = 0; i < 2; i++)
#pragma unroll
        for (int j = 0; j < 8; j++)
#pragma unroll
            for (int c = 0; c < 4; c++) acc[i][j][c] = 0.f;

    // prologue: stages 0,1
#pragma unroll
    for (int s = 0; s < 2; s++) {
        const unsigned da = sbase + (unsigned)(s * 2 * GEMM_TILE) * 4u + soff;
        const unsigned db = da + (unsigned)GEMM_TILE * 4u;
        const __half* a = Ap + s * 64;
        const __half* w = Wp + s * 64;
#pragma unroll
        for (int e = 0; e < 4; e++) { cp16(da + e * 16, a + e * 8); cp16(db + e * 16, w + e * 8); }
        asm volatile("cp.async.commit_group;\n");
    }

    for (int s = 0; s < stages; s++) {
        if (s + 1 < stages) asm volatile("cp.async.wait_group 1;\n");
        else                asm volatile("cp.async.wait_group 0;\n");
        __syncthreads();

        if (s + 2 < stages) {
            const int sn = s + 2;
            const unsigned da = sbase + (unsigned)((sn % 3) * 2 * GEMM_TILE) * 4u + soff;
            const unsigned db = da + (unsigned)GEMM_TILE * 4u;
            const __half* a = Ap + sn * 64;
            const __half* w = Wp + sn * 64;
#pragma unroll
            for (int e = 0; e < 4; e++) { cp16(da + e * 16, a + e * 8); cp16(db + e * 16, w + e * 8); }
            asm volatile("cp.async.commit_group;\n");
        }

        const unsigned* Ab = (const unsigned*)(smf + (s % 3) * 2 * GEMM_TILE);
        const unsigned* Bb = Ab + GEMM_TILE;

        // fragment double buffering across the 4 k16 steps
        unsigned af[2][2][4], bf[2][8][2];
        load_frags(Ab, Bb, wm, wn, gid, t4, 0, af[0], bf[0]);
#pragma unroll
        for (int ks = 0; ks < 4; ks++) {
            if (ks < 3)
                load_frags(Ab, Bb, wm, wn, gid, t4, ks + 1, af[(ks + 1) & 1], bf[(ks + 1) & 1]);
            const int cur = ks & 1;
#pragma unroll
            for (int i = 0; i < 2; i++)
#pragma unroll
                for (int j = 0; j < 8; j++) MMA_F16(acc[i][j], af[cur][i], bf[cur][j]);
        }
    }

    // epilogue
#pragma unroll
    for (int i = 0; i < 2; i++) {
        const int r0 = bm + wm + 16 * i + gid;
#pragma unroll
        for (int j = 0; j < 8; j++) {
            const int col = bn + wn + 8 * j + 2 * t4;
            const float2 bv = *(const float2*)(bias + col);
            float o00 = acc[i][j][0] + bv.x;
            float o01 = acc[i][j][1] + bv.y;
            float o10 = acc[i][j][2] + bv.x;
            float o11 = acc[i][j][3] + bv.y;
            if (HAS_RES) {
                const float2 rv0 = *(const float2*)(res + (size_t)r0 * Nc + col);
                const float2 rv1 = *(const float2*)(res + (size_t)(r0 + 8) * Nc + col);
                o00 += rv0.x; o01 += rv0.y;
                o10 += rv1.x; o11 += rv1.y;
            }
            if (RELU) {
                o00 = fmaxf(o00, 0.f); o01 = fmaxf(o01, 0.f);
                o10 = fmaxf(o10, 0.f); o11 = fmaxf(o11, 0.f);
            }
            if (OUTH) {
                __half* C = (__half*)Cv;
                *(__half2*)(C + (size_t)r0 * Nc + col)       = __floats2half2_rn(o00, o01);
                *(__half2*)(C + (size_t)(r0 + 8) * Nc + col) = __floats2half2_rn(o10, o11);
            } else {
                float* C = (float*)Cv;
                *(float2*)(C + (size_t)r0 * Nc + col)       = make_float2(o00, o01);
                *(float2*)(C + (size_t)(r0 + 8) * Nc + col) = make_float2(o10, o11);
            }
        }
    }
}

template <bool RELU, bool HAS_RES, bool OUTH>
__global__ __launch_bounds__(256, 2)
void gemm_tc(const __half* __restrict__ A, const __half* __restrict__ W,
             const float* __restrict__ bias, const float* __restrict__ res,
             void* __restrict__ C, int Nc, int Kc) {
    extern __shared__ float smf[];
    gemm_body<RELU, HAS_RES, OUTH>(A, W, bias, res, C, Nc, Kc, smf);
}

// fused QKV: blockIdx.z selects weight/bias/output (shared A, one launch)
struct QKVArgs {
    const __half* W[3];
    const float*  b[3];
    float*        o[3];
};
__global__ __launch_bounds__(256, 2)
void gemm_qkv(const __half* __restrict__ A, QKVArgs args) {
    extern __shared__ float smf[];
    const int z = blockIdx.z;
    gemm_body<false, false, false>(A, args.W[z], args.b[z], nullptr, args.o[z], D_, D_, smf);
}

// ---------------------------------------------------------------------------
// Kernel 4: tensor-core attention (tf32 mma, verified R12 structure).
// block = (head, 64-query tile), 256 thr. Output written as fp16 (feeds Wo).
// ---------------------------------------------------------------------------
__global__ __launch_bounds__(256)
void attn_tc(const float* __restrict__ Q, const float* __restrict__ Kx,
             const float* __restrict__ V, const float* __restrict__ bias,
             __half* __restrict__ O) {
    extern __shared__ float sm[];
    float*    Qs  = sm;                 // 64 x 68 (tf32 bits, scaled)
    float*    S   = sm + ATT_Q_;        // 64 x 517 (fp32 -> tf32 probs -> partials)
    float*    ST  = S + ATT_S_;         // K: 256x68 / Vt: 64x261
    unsigned* Qu  = (unsigned*)Qs;
    unsigned* Su  = (unsigned*)S;
    unsigned* STu = (unsigned*)ST;

    const int tid  = threadIdx.x;
    const int warp = tid >> 5, lane = tid & 31;
    const int gid  = lane >> 2, t4 = lane & 3;
    const int hidx = blockIdx.y;        // 0..191
    const int bt   = hidx >> 3;
    const int kh   = hidx & 7;
    const int n0   = blockIdx.x * 64;
    const size_t rowbase = (size_t)bt * N_;
    const size_t headoff = (size_t)kh * DH_;
    const unsigned stbase = (unsigned)__cvta_generic_to_shared(ST);

    // load Q tile (64 x 64), scale by 1/sqrt(64)=0.125, RNA->tf32
    for (int i = tid; i < 64 * 16; i += 256) {
        const int r = i >> 4, c = (i & 15) << 2;
        const float4 vv = *(const float4*)(Q + (rowbase + n0 + r) * D_ + headoff + c);
        unsigned* qd = Qu + r * 68 + c;
        qd[0] = f2tf32(vv.x * 0.125f); qd[1] = f2tf32(vv.y * 0.125f);
        qd[2] = f2tf32(vv.z * 0.125f); qd[3] = f2tf32(vv.w * 0.125f);
    }

    // ---- phase 1: S = Q K^T + bias (2 chunks of 256 keys) ----------------
    const int wq = (warp & 1) * 32;     // query tile base
    const int wk = (warp >> 1) * 64;    // key base within chunk
    for (int ch = 0; ch < 2; ch++) {
        const int m0 = ch * 256;
        __syncthreads();
        for (int i = tid; i < 256 * 4; i += 256) {
            const int r = i >> 2, c = (i & 3) << 4;
            const unsigned dst = stbase + (unsigned)(r * 68 + c) * 4u;
            const float* src = Kx + (rowbase + m0 + r) * D_ + headoff + c;
            cp16(dst,      src);
            cp16(dst + 16, src + 4);
            cp16(dst + 32, src + 8);
            cp16(dst + 48, src + 12);
        }
        asm volatile("cp.async.commit_group;\n");
        asm volatile("cp.async.wait_group 0;\n");
        __syncthreads();

        float acc[2][8][4];
#pragma unroll
        for (int i = 0; i < 2; i++)
#pragma unroll
            for (int j = 0; j < 8; j++)
#pragma unroll
                for (int c = 0; c < 4; c++) acc[i][j][c] = 0.f;

#pragma unroll
        for (int ks = 0; ks < 8; ks++) {
            unsigned af[2][4], bf[8][2];
#pragma unroll
            for (int i = 0; i < 2; i++) {
                const unsigned* p = Qu + (wq + 16 * i + gid) * 68 + ks * 8 + t4;
                af[i][0] = p[0]; af[i][1] = p[8 * 68]; af[i][2] = p[4]; af[i][3] = p[8 * 68 + 4];
            }
#pragma unroll
            for (int j = 0; j < 8; j++) {
                const unsigned* p = STu + (wk + 8 * j + gid) * 68 + ks * 8 + t4;
                bf[j][0] = p[0]; bf[j][1] = p[4];
            }
#pragma unroll
            for (int i = 0; i < 2; i++)
#pragma unroll
                for (int j = 0; j < 8; j++) MMA_TF32(acc[i][j], af[i], bf[j]);
        }

        // store S (+bias)
#pragma unroll
        for (int i = 0; i < 2; i++) {
            const int r0 = wq + 16 * i + gid;
#pragma unroll
            for (int j = 0; j < 8; j++) {
                const int col = wk + 8 * j + 2 * t4;      // within chunk
                const float2 b0 = *(const float2*)(bias + (size_t)(n0 + r0) * N_ + m0 + col);
                const float2 b1 = *(const float2*)(bias + (size_t)(n0 + r0 + 8) * N_ + m0 + col);
                S[r0 * 517 + m0 + col]           = acc[i][j][0] + b0.x;
                S[r0 * 517 + m0 + col + 1]       = acc[i][j][1] + b0.y;
                S[(r0 + 8) * 517 + m0 + col]     = acc[i][j][2] + b1.x;
                S[(r0 + 8) * 517 + m0 + col + 1] = acc[i][j][3] + b1.y;
            }
        }
    }
    __syncthreads();

    // ---- phase 2: exact row softmax; rewrite P as RNA tf32 ---------------
    {
#pragma unroll
        for (int ii = 0; ii < 8; ii++) {
            float*    row  = S  + (warp * 8 + ii) * 517;
            unsigned* rowu = Su + (warp * 8 + ii) * 517;
            float mx = -3.4e38f;
            for (int m = lane; m < N_; m += 32) mx = fmaxf(mx, row[m]);
#pragma unroll
            for (int o = 16; o; o >>= 1) mx = fmaxf(mx, __shfl_xor_sync(0xffffffffu, mx, o));
            float sum = 0.f;
            for (int m = lane; m < N_; m += 32) {
                const float e = __expf(row[m] - mx);
                row[m] = e;
                sum += e;
            }
#pragma unroll
            for (int o = 16; o; o >>= 1) sum += __shfl_xor_sync(0xffffffffu, sum, o);
            const float inv = 1.f / sum;
            for (int m = lane; m < N_; m += 32) rowu[m] = f2tf32(row[m] * inv);
        }
    }

    // ---- phase 3: O = P V. warp = (query-half, 64-key split of chunk) ----
    const int wq3 = (warp & 1) * 32;    // query tile base
    const int kg  = warp >> 1;          // 0..3: 64-key group within chunk
    float acc3[2][8][4];
#pragma unroll
    for (int i = 0; i < 2; i++)
#pragma unroll
        for (int j = 0; j < 8; j++)
#pragma unroll
            for (int c = 0; c < 4; c++) acc3[i][j][c] = 0.f;

    for (int ch = 0; ch < 2; ch++) {
        const int m0 = ch * 256;
        __syncthreads();
        // stage Vt[d][m] (transposed, RNA->tf32), stride 261
        for (int i = tid; i < 256 * 16; i += 256) {
            const int r = i >> 4, c = (i & 15) << 2;   // r = key, c = d
            const float4 vv = *(const float4*)(V + (rowbase + m0 + r) * D_ + headoff + c);
            STu[(c + 0) * 261 + r] = f2tf32(vv.x);
            STu[(c + 1) * 261 + r] = f2tf32(vv.y);
            STu[(c + 2) * 261 + r] = f2tf32(vv.z);
            STu[(c + 3) * 261 + r] = f2tf32(vv.w);
        }
        __syncthreads();

#pragma unroll
        for (int ks = 0; ks < 8; ks++) {
            unsigned af[2][4], bf[8][2];
#pragma unroll
            for (int i = 0; i < 2; i++) {
                const unsigned* p = Su + (wq3 + 16 * i + gid) * 517 + m0 + kg * 64 + ks * 8 + t4;
                af[i][0] = p[0]; af[i][1] = p[8 * 517]; af[i][2] = p[4]; af[i][3] = p[8 * 517 + 4];
            }
#pragma unroll
            for (int j = 0; j < 8; j++) {
                const unsigned* p = STu + (8 * j + gid) * 261 + kg * 64 + ks * 8 + t4;
                bf[j][0] = p[0]; bf[j][1] = p[4];
            }
#pragma unroll
            for (int i = 0; i < 2; i++)
#pragma unroll
                for (int j = 0; j < 8; j++) MMA_TF32(acc3[i][j], af[i], bf[j]);
        }
    }

    // reduce the 4 k-split partials through smem (reuse S region, stride 68)
    __syncthreads();
    {
        float* part = S + warp * (32 * 68);
#pragma unroll
        for (int i = 0; i < 2; i++) {
            const int r = 16 * i + gid;
#pragma unroll
            for (int j = 0; j < 8; j++) {
                const int c = 8 * j + 2 * t4;
                *(float2*)(part + r * 68 + c)       = make_float2(acc3[i][j][0], acc3[i][j][1]);
                *(float2*)(part + (r + 8) * 68 + c) = make_float2(acc3[i][j][2], acc3[i][j][3]);
            }
        }
    }
    __syncthreads();

    // sum over kg and write O (fp16)
    for (int i = tid; i < 64 * 16; i += 256) {
        const int q  = i >> 4, dc = (i & 15) << 2;
        const int mt = q >> 5, qi = q & 31;
        float4 o = make_float4(0.f, 0.f, 0.f, 0.f);
#pragma unroll
        for (int kg2 = 0; kg2 < 4; kg2++) {
            const float4 p = *(const float4*)(S + (kg2 * 2 + mt) * (32 * 68) + qi * 68 + dc);
            o.x += p.x; o.y += p.y; o.z += p.z; o.w += p.w;
        }
        __half2* op = (__half2*)(O + (rowbase + n0 + q) * D_ + headoff + dc);
        op[0] = __floats2half2_rn(o.x, o.y);
        op[1] = __floats2half2_rn(o.z, o.w);
    }
}

// ---------------------------------------------------------------------------
// Launch
// ---------------------------------------------------------------------------
extern "C" void kernel_launch(void* const* d_in, const int* in_sizes, int n_in,
                              void* d_out, int out_size) {
    (void)in_sizes; (void)n_in; (void)out_size;
    const float* x    = (const float*)d_in[0];
    const float* lap  = (const float*)d_in[1];
    const float* ne   = (const float*)d_in[2];
    const float* Wq   = (const float*)d_in[3];
    const float* bq   = (const float*)d_in[4];
    const float* Wk   = (const float*)d_in[5];
    const float* bk   = (const float*)d_in[6];
    const float* Wv   = (const float*)d_in[7];
    const float* bv   = (const float*)d_in[8];
    const float* Wo   = (const float*)d_in[9];
    const float* bo   = (const float*)d_in[10];
    const float* W1   = (const float*)d_in[11];
    const float* b1   = (const float*)d_in[12];
    const float* W2   = (const float*)d_in[13];
    const float* b2   = (const float*)d_in[14];
    const float* g1   = (const float*)d_in[15];
    const float* be1  = (const float*)d_in[16];
    const float* g2   = (const float*)d_in[17];
    const float* be2  = (const float*)d_in[18];
    const float* alp  = (const float*)d_in[19];
    const float* bet  = (const float*)d_in[20];
    float* out = (float*)d_out;

    float *q, *k, *v, *x1, *bias;
    __half *xnh, *hh, *aoh, *hidh, *wqh, *wkh, *wvh, *woh, *w1h, *w2h;
    cudaGetSymbolAddress((void**)&q,    g_q);
    cudaGetSymbolAddress((void**)&k,    g_k);
    cudaGetSymbolAddress((void**)&v,    g_v);
    cudaGetSymbolAddress((void**)&x1,   g_x1);
    cudaGetSymbolAddress((void**)&bias, g_bias);
    cudaGetSymbolAddress((void**)&xnh,  g_xnh);
    cudaGetSymbolAddress((void**)&hh,   g_hh);
    cudaGetSymbolAddress((void**)&aoh,  g_aoh);
    cudaGetSymbolAddress((void**)&hidh, g_hidh);
    cudaGetSymbolAddress((void**)&wqh,  g_wqh);
    cudaGetSymbolAddress((void**)&wkh,  g_wkh);
    cudaGetSymbolAddress((void**)&wvh,  g_wvh);
    cudaGetSymbolAddress((void**)&woh,  g_woh);
    cudaGetSymbolAddress((void**)&w1h,  g_w1h);
    cudaGetSymbolAddress((void**)&w2h,  g_w2h);

    cudaFuncSetAttribute(attn_tc,
                         cudaFuncAttributeMaxDynamicSharedMemorySize, ATT_SMEM);
    cudaFuncSetAttribute(gemm_qkv,
                         cudaFuncAttributeMaxDynamicSharedMemorySize, GEMM_SMEM);
    cudaFuncSetAttribute(gemm_tc<false, true, false>,
                         cudaFuncAttributeMaxDynamicSharedMemorySize, GEMM_SMEM);
    cudaFuncSetAttribute(gemm_tc<true, false, true>,
                         cudaFuncAttributeMaxDynamicSharedMemorySize, GEMM_SMEM);

    // 0) weights -> fp16
    cvt_f2h<<<256, 256>>>(Wq, wqh, D_ * D_ / 4);
    cvt_f2h<<<256, 256>>>(Wk, wkh, D_ * D_ / 4);
    cvt_f2h<<<256, 256>>>(Wv, wvh, D_ * D_ / 4);
    cvt_f2h<<<256, 256>>>(Wo, woh, D_ * D_ / 4);
    cvt_f2h<<<512, 256>>>(W1, w1h, DFF_ * D_ / 4);
    cvt_f2h<<<512, 256>>>(W2, w2h, D_ * DFF_ / 4);

    // 1) graph bias (b,t,k-invariant)
    bias_kernel<<<N_, N_>>>(ne, lap, alp, bet, bias);

    // 2) LN1 -> fp16
    ln_kernel<<<ROWS_, 128>>>(x, g1, be1, xnh);

    // 3) Q/K/V projections — fused single launch (fp16 mma, fp32 out)
    const dim3 thr(256);
    QKVArgs qa;
    qa.W[0] = wqh; qa.W[1] = wkh; qa.W[2] = wvh;
    qa.b[0] = bq;  qa.b[1] = bk;  qa.b[2] = bv;
    qa.o[0] = q;   qa.o[1] = k;   qa.o[2] = v;
    gemm_qkv<<<dim3(D_ / 128, ROWS_ / 128, 3), thr, GEMM_SMEM>>>(xnh, qa);

    // 4) attention (192 heads x 8 query tiles) -> fp16 ao
    attn_tc<<<dim3(N_ / 64, BT_ * KH_), thr, ATT_SMEM>>>(q, k, v, bias, aoh);

    // 5) output projection + residual (x) -> fp32 x1
    gemm_tc<false, true, false><<<dim3(D_ / 128, ROWS_ / 128), thr, GEMM_SMEM>>>(
        aoh, woh, bo, x, x1, D_, D_);

    // 6) LN2 -> fp16
    ln_kernel<<<ROWS_, 128>>>(x1, g2, be2, hh);

    // 7) FFN1 with fused ReLU -> fp16 hid
    gemm_tc<true, false, true><<<dim3(DFF_ / 128, ROWS_ / 128), thr, GEMM_SMEM>>>(
        hh, w1h, b1, nullptr, hidh, DFF_, D_);

    // 8) FFN2 + residual (x1) -> fp32 output
    gemm_tc<false, true, false><<<dim3(D_ / 128, ROWS_ / 128), thr, GEMM_SMEM>>>(
        hidh, w2h, b2, x1, out, D_, DFF_);
}